// round 1
// baseline (speedup 1.0000x reference)
#include <cuda_runtime.h>
#include <math.h>

#define N_NODES 20000
#define N_EDGES 320000
#define D 128
#define H 8
#define PH 16
#define G 64
#define LN_EPS 1e-5f

#define WIDTH   (5.0f / 63.0f)
#define INV_W   (63.0f / 5.0f)
#define EXP_COEF (-0.5f * INV_W * INV_W)
#define PI_OVER_CUT 0.62831853071795864f
#define INV_SQRT_P 0.25f

// ---------------- scratch (device globals, no runtime allocation) ----------------
static __device__ __align__(16) float g_q[(size_t)N_EDGES * D];     // 164 MB: layernormed q per edge
static __device__ float g_C[N_EDGES];                               // cutoff per edge
static __device__ float g_logit[(size_t)N_EDGES * H];               // 10 MB
static __device__ __align__(16) float g_qv[(size_t)N_NODES * D];    // q_vec per node
static __device__ __align__(16) float g_gk[(size_t)N_NODES * H * D];// 82 MB
static __device__ float g_h2[(size_t)N_NODES * D];
static __device__ int g_hist[N_NODES];
static __device__ int g_off[N_NODES + 1];
static __device__ int g_cursor[N_NODES];
static __device__ int g_eorder[N_EDGES];

// ---------------- K0: zero histogram ----------------
__global__ void k0_init() {
    int i = blockIdx.x * blockDim.x + threadIdx.x;
    if (i < N_NODES) g_hist[i] = 0;
}

// ---------------- K1: per-edge filter + cutoff + q = LN(W*h1[dst]+t) ----------------
// 128 threads = one d-column each; 8 edges per block.
__global__ void __launch_bounds__(128) k1_edge(
    const float* __restrict__ pos, const float* __restrict__ h1,
    const float* __restrict__ t,   const float* __restrict__ fw,
    const float* __restrict__ fb,  const float* __restrict__ ln_g,
    const float* __restrict__ ln_b,const int* __restrict__ src,
    const int* __restrict__ dst,   float* __restrict__ outW)
{
    __shared__ float sh_fw[G * D];   // 32 KB
    __shared__ float sh_f[32];
    __shared__ float sh_red[4];
    const int tid = threadIdx.x;

    for (int i = tid; i < G * D; i += 128) sh_fw[i] = fw[i];
    __syncthreads();

    float colsum = 0.f;
    #pragma unroll
    for (int g = 0; g < G; g++) colsum += sh_fw[g * D + tid];
    const float fbd = fb[tid], lg = ln_g[tid], lb = ln_b[tid];

    const int e0 = blockIdx.x * 8;
    #pragma unroll 1
    for (int ei = 0; ei < 8; ei++) {
        const int e = e0 + ei;            // E divisible by 8
        const int s = src[e], dn = dst[e];
        const float dx = pos[dn*3+0] - pos[s*3+0];
        const float dy = pos[dn*3+1] - pos[s*3+1];
        const float dz = pos[dn*3+2] - pos[s*3+2];
        const float r  = sqrtf(dx*dx + dy*dy + dz*dz);
        const float C  = (r < 5.0f) ? 0.5f * (__cosf(r * PI_OVER_CUT) + 1.0f) : 0.0f;

        // gaussian window: only |r - offset| <= 9.5*width matters (exp(-45) cut)
        const int i0  = (int)floorf(r * INV_W + 0.5f);
        const int glo = max(0, i0 - 9);
        const int ghi = min(G - 1, i0 + 9);
        const int nwin = ghi - glo + 1;   // <= 19
        if (tid < nwin) {
            float dr = r - (glo + tid) * WIDTH;
            sh_f[tid] = __expf(EXP_COEF * dr * dr);
        }
        __syncthreads();

        float acc = 0.f;
        for (int j = 0; j < nwin; j++)
            acc += sh_f[j] * sh_fw[(glo + j) * D + tid];
        const float W = (2.0f * acc - colsum + fbd) * C;
        outW[(size_t)e * D + tid] = W;

        float v = W * h1[(size_t)dn * D + tid] + t[(size_t)e * D + tid];

        // layernorm over 128 threads
        float sm = v;
        #pragma unroll
        for (int o = 16; o; o >>= 1) sm += __shfl_xor_sync(0xffffffffu, sm, o);
        if ((tid & 31) == 0) sh_red[tid >> 5] = sm;
        __syncthreads();
        const float mu = (sh_red[0] + sh_red[1] + sh_red[2] + sh_red[3]) * (1.0f / D);
        const float dv = v - mu;
        float vs = dv * dv;
        #pragma unroll
        for (int o = 16; o; o >>= 1) vs += __shfl_xor_sync(0xffffffffu, vs, o);
        __syncthreads();                       // everyone done reading sh_red
        if ((tid & 31) == 0) sh_red[tid >> 5] = vs;
        __syncthreads();
        const float var = (sh_red[0] + sh_red[1] + sh_red[2] + sh_red[3]) * (1.0f / D);
        g_q[(size_t)e * D + tid] = dv * rsqrtf(var + LN_EPS) * lg + lb;

        if (tid == 0) { g_C[e] = C; atomicAdd(&g_hist[s], 1); }
        __syncthreads();                       // sh_f / sh_red reuse next edge
    }
}

// ---------------- K2: single-block exclusive scan of histogram ----------------
__global__ void k2_scan() {
    __shared__ int sh[256];
    const int tid = threadIdx.x;
    const int CH = (N_NODES + 255) / 256;     // 79
    const int lo = tid * CH;
    const int hi = min(lo + CH, N_NODES);
    int s = 0;
    for (int i = lo; i < hi; i++) s += g_hist[i];
    sh[tid] = s;
    __syncthreads();
    for (int off = 1; off < 256; off <<= 1) {
        int v = (tid >= off) ? sh[tid - off] : 0;
        __syncthreads();
        sh[tid] += v;
        __syncthreads();
    }
    int base = (tid == 0) ? 0 : sh[tid - 1];
    for (int i = lo; i < hi; i++) {
        int c = g_hist[i];
        g_off[i] = base;
        g_cursor[i] = base;
        base += c;
    }
    if (tid == 0) g_off[N_NODES] = N_EDGES;
}

// ---------------- K3: scatter edges into src-sorted order ----------------
__global__ void k3_scatter(const int* __restrict__ src) {
    for (int e = blockIdx.x * blockDim.x + threadIdx.x; e < N_EDGES;
         e += gridDim.x * blockDim.x) {
        int p = atomicAdd(&g_cursor[src[e]], 1);
        g_eorder[p] = e;
    }
}

// ---------------- K4: qv[n] = q[q_id[n]] @ Wq ----------------
__global__ void __launch_bounds__(128) k4_qv(const float* __restrict__ Wq,
                                             const int* __restrict__ q_id) {
    extern __shared__ float sm[];
    float* shW = sm;            // D*D
    float* shx = sm + D * D;    // D
    const int tid = threadIdx.x;
    for (int i = tid; i < D * D; i += 128) shW[i] = Wq[i];
    __syncthreads();
    for (int n = blockIdx.x; n < N_NODES; n += gridDim.x) {
        shx[tid] = g_q[(size_t)q_id[n] * D + tid];
        __syncthreads();
        float acc = 0.f;
        #pragma unroll 16
        for (int k = 0; k < D; k++) acc += shx[k] * shW[k * D + tid];
        g_qv[(size_t)n * D + tid] = acc;
        __syncthreads();
    }
}

// ---------------- K5: gk[n,h,d] = sum_p Wk[d, h*16+p] * qv[n, h*16+p] ----------------
__global__ void __launch_bounds__(128) k5_gk(const float* __restrict__ Wk) {
    extern __shared__ float sm[];
    float* shWT = sm;               // transposed [j][d], row stride 129 (conflict-free)
    float* shx  = sm + 128 * 129;   // qv row
    const int tid = threadIdx.x;
    for (int i = tid; i < D * D; i += 128) {
        int dd = i >> 7, j = i & 127;
        shWT[j * 129 + dd] = Wk[i];
    }
    __syncthreads();
    for (int n = blockIdx.x; n < N_NODES; n += gridDim.x) {
        shx[tid] = g_qv[(size_t)n * D + tid];
        __syncthreads();
        #pragma unroll
        for (int h = 0; h < H; h++) {
            float acc = 0.f;
            #pragma unroll
            for (int p = 0; p < PH; p++) {
                int j = h * PH + p;
                acc += shWT[j * 129 + tid] * shx[j];
            }
            g_gk[((size_t)n * H + h) * D + tid] = acc;
        }
        __syncthreads();
    }
}

// ---------------- K7: per-node logits, softmax, Y accumulation, h2 = Y @ Wv(head) ----------------
__global__ void __launch_bounds__(128) k7_node(const float* __restrict__ Wv) {
    extern __shared__ float sm[];
    float* shWv  = sm;                  // D*D  (64 KB)
    float* shG   = sm + D * D;          // H*D : gk first, then reused for Y
    float* shm   = shG + H * D;         // 8
    float* shsin = shm + H;             // 8
    float* shatt = shsin + H;           // 8
    float* shred = shatt + H;           // 4*H
    const int tid  = threadIdx.x;
    const int lane = tid & 31;
    const int w    = tid >> 5;

    for (int i = tid; i < D * D; i += 128) shWv[i] = Wv[i];
    __syncthreads();

    for (int n = blockIdx.x; n < N_NODES; n += gridDim.x) {
        const int base = g_off[n];
        const int deg  = g_off[n + 1] - base;
        if (deg == 0) { g_h2[(size_t)n * D + tid] = 0.f; continue; }

        #pragma unroll
        for (int h = 0; h < H; h++)
            shG[h * D + tid] = g_gk[((size_t)n * H + h) * D + tid];
        __syncthreads();

        // ---- pass 0: logits + running max (warp per edge) ----
        float lmax[H];
        #pragma unroll
        for (int h = 0; h < H; h++) lmax[h] = -1e30f;
        for (int i = w; i < deg; i += 4) {
            const int e = g_eorder[base + i];
            const float4 q4 = *(const float4*)&g_q[(size_t)e * D + lane * 4];
            float myl = 0.f;
            #pragma unroll
            for (int h = 0; h < H; h++) {
                const float4 g4 = *(const float4*)&shG[h * D + lane * 4];
                float p = q4.x*g4.x + q4.y*g4.y + q4.z*g4.z + q4.w*g4.w;
                #pragma unroll
                for (int o = 16; o; o >>= 1) p += __shfl_xor_sync(0xffffffffu, p, o);
                p *= INV_SQRT_P;
                if (lane == h) myl = p;
                lmax[h] = fmaxf(lmax[h], p);
            }
            if (lane < H) g_logit[(size_t)e * H + lane] = myl;
        }
        if (lane == 0) {
            #pragma unroll
            for (int h = 0; h < H; h++) shred[w * H + h] = lmax[h];
        }
        __syncthreads();
        if (tid < H)
            shm[tid] = fmaxf(fmaxf(shred[tid], shred[H + tid]),
                             fmaxf(shred[2 * H + tid], shred[3 * H + tid]));
        __syncthreads();

        // ---- pass 1: s = sum exp(l-m)*C (z cancels analytically) ----
        float lsum = 0.f;
        if (lane < H) {
            for (int i = w; i < deg; i += 4) {
                const int e = g_eorder[base + i];
                lsum += __expf(g_logit[(size_t)e * H + lane] - shm[lane]) * g_C[e];
            }
            shred[w * H + lane] = lsum;
        }
        __syncthreads();
        if (tid < H)
            shsin[tid] = 1.0f / (shred[tid] + shred[H + tid] +
                                 shred[2 * H + tid] + shred[3 * H + tid]);
        __syncthreads();

        // ---- pass 2: Y[h,d] += att[e,h] * q[e,d] ----
        float acc[H];
        #pragma unroll
        for (int h = 0; h < H; h++) acc[h] = 0.f;
        for (int i = 0; i < deg; i++) {
            const int e = g_eorder[base + i];
            if (tid < H)
                shatt[tid] = __expf(g_logit[(size_t)e * H + tid] - shm[tid]) *
                             g_C[e] * shsin[tid];
            __syncthreads();
            const float qd = g_q[(size_t)e * D + tid];
            #pragma unroll
            for (int h = 0; h < H; h++) acc[h] += shatt[h] * qd;
            __syncthreads();
        }

        // Y -> shared (reuse shG), then h2[col j] = sum_d Y[j/16, d] * Wv[d, j]
        #pragma unroll
        for (int h = 0; h < H; h++) shG[h * D + tid] = acc[h];
        __syncthreads();
        const int hh = tid >> 4;
        float hv = 0.f;
        #pragma unroll 16
        for (int d0 = 0; d0 < D; d0++) hv += shG[hh * D + d0] * shWv[d0 * D + tid];
        g_h2[(size_t)n * D + tid] = hv;
        __syncthreads();
    }
}

// ---------------- K8: m_agg = h2 @ Wo ----------------
__global__ void __launch_bounds__(128) k8_out(const float* __restrict__ Wo,
                                              float* __restrict__ outM) {
    extern __shared__ float sm[];
    float* shW = sm;
    float* shx = sm + D * D;
    const int tid = threadIdx.x;
    for (int i = tid; i < D * D; i += 128) shW[i] = Wo[i];
    __syncthreads();
    for (int n = blockIdx.x; n < N_NODES; n += gridDim.x) {
        shx[tid] = g_h2[(size_t)n * D + tid];
        __syncthreads();
        float acc = 0.f;
        #pragma unroll 16
        for (int k = 0; k < D; k++) acc += shx[k] * shW[k * D + tid];
        outM[(size_t)n * D + tid] = acc;
        __syncthreads();
    }
}

// ---------------- launch ----------------
extern "C" void kernel_launch(void* const* d_in, const int* in_sizes, int n_in,
                              void* d_out, int out_size) {
    const float* pos  = (const float*)d_in[0];
    const float* h1   = (const float*)d_in[1];
    const float* t    = (const float*)d_in[2];
    const float* fw   = (const float*)d_in[3];
    const float* fb   = (const float*)d_in[4];
    const float* ln_g = (const float*)d_in[5];
    const float* ln_b = (const float*)d_in[6];
    const float* Wq   = (const float*)d_in[7];
    const float* Wk   = (const float*)d_in[8];
    const float* Wv   = (const float*)d_in[9];
    const float* Wo   = (const float*)d_in[10];
    const int* src    = (const int*)d_in[11];
    const int* dst    = (const int*)d_in[12];
    const int* q_id   = (const int*)d_in[13];

    float* out  = (float*)d_out;
    float* outM = out;                              // m_agg [N,D]
    float* outW = out + (size_t)N_NODES * D;        // W     [E,D]

    const size_t sm_mat = (size_t)(D * D + D) * sizeof(float);          // 66,048
    const size_t sm_gk  = (size_t)(128 * 129 + 128) * sizeof(float);    // 66,560
    const size_t sm_k7  = (size_t)(D * D + H * D + 3 * H + 4 * H) * sizeof(float); // ~70 KB

    cudaFuncSetAttribute(k4_qv,   cudaFuncAttributeMaxDynamicSharedMemorySize, (int)sm_mat);
    cudaFuncSetAttribute(k5_gk,   cudaFuncAttributeMaxDynamicSharedMemorySize, (int)sm_gk);
    cudaFuncSetAttribute(k7_node, cudaFuncAttributeMaxDynamicSharedMemorySize, (int)sm_k7);
    cudaFuncSetAttribute(k8_out,  cudaFuncAttributeMaxDynamicSharedMemorySize, (int)sm_mat);

    k0_init<<<(N_NODES + 255) / 256, 256>>>();
    k1_edge<<<N_EDGES / 8, 128>>>(pos, h1, t, fw, fb, ln_g, ln_b, src, dst, outW);
    k2_scan<<<1, 256>>>();
    k3_scatter<<<256, 256>>>(src);
    k4_qv<<<444, 128, sm_mat>>>(Wq, q_id);
    k5_gk<<<444, 128, sm_gk>>>(Wk);
    k7_node<<<444, 128, sm_k7>>>(Wv);
    k8_out<<<444, 128, sm_mat>>>(Wo, outM);
}

// round 2
// speedup vs baseline: 1.0119x; 1.0119x over previous
#include <cuda_runtime.h>
#include <math.h>

#define N_NODES 20000
#define N_EDGES 320000
#define D 128
#define H 8
#define PH 16
#define G 64
#define LN_EPS 1e-5f
#define MAXD 256

#define WIDTH   (5.0f / 63.0f)
#define INV_W   (63.0f / 5.0f)
#define EXP_COEF (-0.5f * INV_W * INV_W)
#define PI_OVER_CUT 0.62831853071795864f
#define INV_SQRT_P 0.25f

// ---------------- scratch (device globals, no runtime allocation) ----------------
static __device__ __align__(16) float g_q[(size_t)N_EDGES * D];     // layernormed q per edge
static __device__ float g_C[N_EDGES];                               // cutoff per edge
static __device__ float g_logit[(size_t)N_EDGES * H];               // fallback only (deg > MAXD)
static __device__ __align__(16) float g_qv[(size_t)N_NODES * D];
static __device__ __align__(16) float g_gk[(size_t)N_NODES * H * D];
static __device__ float g_h2[(size_t)N_NODES * D];
static __device__ int g_hist[N_NODES];
static __device__ int g_off[N_NODES + 1];
static __device__ int g_cursor[N_NODES];
static __device__ int g_eorder[N_EDGES];

// ---------------- K0: zero histogram ----------------
__global__ void k0_init() {
    int i = blockIdx.x * blockDim.x + threadIdx.x;
    if (i < N_NODES) g_hist[i] = 0;
}

// ---------------- K1: per-edge filter + cutoff + q = LN(W*h1[dst]+t) ----------------
// 128 threads = one d-column each; 8 edges per block; 2 barriers/edge via parity buffers.
__global__ void __launch_bounds__(128) k1_edge(
    const float* __restrict__ pos, const float* __restrict__ h1,
    const float* __restrict__ t,   const float* __restrict__ fw,
    const float* __restrict__ fb,  const float* __restrict__ ln_g,
    const float* __restrict__ ln_b,const int* __restrict__ src,
    const int* __restrict__ dst,   float* __restrict__ outW)
{
    __shared__ float sh_fw[G * D];       // 32 KB
    __shared__ float sh_f[2][20];
    __shared__ float2 sh_red[2][4];
    const int tid = threadIdx.x;

    for (int i = tid; i < G * D; i += 128) sh_fw[i] = fw[i];
    __syncthreads();

    float colsum = 0.f;
    #pragma unroll
    for (int g = 0; g < G; g++) colsum += sh_fw[g * D + tid];
    const float fbd = fb[tid], lg = ln_g[tid], lb = ln_b[tid];

    const int e0 = blockIdx.x * 8;
    #pragma unroll 1
    for (int ei = 0; ei < 8; ei++) {
        const int e = e0 + ei;
        const int p = ei & 1;
        const int s = src[e], dn = dst[e];
        const float dx = pos[dn*3+0] - pos[s*3+0];
        const float dy = pos[dn*3+1] - pos[s*3+1];
        const float dz = pos[dn*3+2] - pos[s*3+2];
        const float r  = sqrtf(dx*dx + dy*dy + dz*dz);
        const float C  = (r < 5.0f) ? 0.5f * (__cosf(r * PI_OVER_CUT) + 1.0f) : 0.0f;

        const int i0  = (int)floorf(r * INV_W + 0.5f);
        const int glo = max(0, i0 - 9);
        const int ghi = min(G - 1, i0 + 9);
        const int nwin = ghi - glo + 1;   // <= 19
        if (tid < nwin) {
            float dr = r - (glo + tid) * WIDTH;
            sh_f[p][tid] = __expf(EXP_COEF * dr * dr);
        }
        __syncthreads();                                    // sync 1

        float acc = 0.f;
        for (int j = 0; j < nwin; j++)
            acc += sh_f[p][j] * sh_fw[(glo + j) * D + tid];
        const float W = (2.0f * acc - colsum + fbd) * C;
        outW[(size_t)e * D + tid] = W;

        const float v = W * h1[(size_t)dn * D + tid] + t[(size_t)e * D + tid];

        // fused sum / sumsq reduction over 128 threads
        float sm = v, sq = v * v;
        #pragma unroll
        for (int o = 16; o; o >>= 1) {
            sm += __shfl_xor_sync(0xffffffffu, sm, o);
            sq += __shfl_xor_sync(0xffffffffu, sq, o);
        }
        if ((tid & 31) == 0) sh_red[p][tid >> 5] = make_float2(sm, sq);
        __syncthreads();                                    // sync 2
        const float2 r0 = sh_red[p][0], r1 = sh_red[p][1],
                     r2 = sh_red[p][2], r3 = sh_red[p][3];
        const float mu  = (r0.x + r1.x + r2.x + r3.x) * (1.0f / D);
        const float ex2 = (r0.y + r1.y + r2.y + r3.y) * (1.0f / D);
        const float var = ex2 - mu * mu;
        g_q[(size_t)e * D + tid] = (v - mu) * rsqrtf(var + LN_EPS) * lg + lb;

        if (tid == 0) { g_C[e] = C; atomicAdd(&g_hist[s], 1); }
        // no trailing barrier: next iter uses parity 1-p buffers
    }
}

// ---------------- K2: single-block exclusive scan of histogram ----------------
__global__ void k2_scan() {
    __shared__ int sh[256];
    const int tid = threadIdx.x;
    const int CH = (N_NODES + 255) / 256;
    const int lo = tid * CH;
    const int hi = min(lo + CH, N_NODES);
    int s = 0;
    for (int i = lo; i < hi; i++) s += g_hist[i];
    sh[tid] = s;
    __syncthreads();
    for (int off = 1; off < 256; off <<= 1) {
        int v = (tid >= off) ? sh[tid - off] : 0;
        __syncthreads();
        sh[tid] += v;
        __syncthreads();
    }
    int base = (tid == 0) ? 0 : sh[tid - 1];
    for (int i = lo; i < hi; i++) {
        int c = g_hist[i];
        g_off[i] = base;
        g_cursor[i] = base;
        base += c;
    }
    if (tid == 0) g_off[N_NODES] = N_EDGES;
}

// ---------------- K3: scatter edges into src-sorted order ----------------
__global__ void k3_scatter(const int* __restrict__ src) {
    for (int e = blockIdx.x * blockDim.x + threadIdx.x; e < N_EDGES;
         e += gridDim.x * blockDim.x) {
        int p = atomicAdd(&g_cursor[src[e]], 1);
        g_eorder[p] = e;
    }
}

// ---------------- K4: qv[n] = q[q_id[n]] @ Wq ----------------
__global__ void __launch_bounds__(128) k4_qv(const float* __restrict__ Wq,
                                             const int* __restrict__ q_id) {
    extern __shared__ float sm[];
    float* shW = sm;
    float* shx = sm + D * D;
    const int tid = threadIdx.x;
    for (int i = tid; i < D * D; i += 128) shW[i] = Wq[i];
    __syncthreads();
    for (int n = blockIdx.x; n < N_NODES; n += gridDim.x) {
        shx[tid] = g_q[(size_t)q_id[n] * D + tid];
        __syncthreads();
        float acc = 0.f;
        #pragma unroll 16
        for (int k = 0; k < D; k++) acc += shx[k] * shW[k * D + tid];
        g_qv[(size_t)n * D + tid] = acc;
        __syncthreads();
    }
}

// ---------------- K5: gk[n,h,d] = sum_p Wk[d, h*16+p] * qv[n, h*16+p] ----------------
__global__ void __launch_bounds__(128) k5_gk(const float* __restrict__ Wk) {
    extern __shared__ float sm[];
    float* shWT = sm;               // [j][d] transposed, stride 129
    float* shx  = sm + 128 * 129;
    const int tid = threadIdx.x;
    for (int i = tid; i < D * D; i += 128) {
        int dd = i >> 7, j = i & 127;
        shWT[j * 129 + dd] = Wk[i];
    }
    __syncthreads();
    for (int n = blockIdx.x; n < N_NODES; n += gridDim.x) {
        shx[tid] = g_qv[(size_t)n * D + tid];
        __syncthreads();
        #pragma unroll
        for (int h = 0; h < H; h++) {
            float acc = 0.f;
            #pragma unroll
            for (int p = 0; p < PH; p++) {
                int j = h * PH + p;
                acc += shWT[j * 129 + tid] * shx[j];
            }
            g_gk[((size_t)n * H + h) * D + tid] = acc;
        }
        __syncthreads();
    }
}

// ---------------- K7: per-node logits + softmax + Y + h2 = Y @ Wv ----------------
// 4 warps stride the node's edges; logits in SMEM; barrier-free edge loops.
__global__ void __launch_bounds__(128) k7_node(const float* __restrict__ Wv) {
    extern __shared__ float sm[];
    float* shWv  = sm;                       // D*D           (64 KB)
    float* shG   = shWv + D * D;             // H*D  (gk, then Y)
    float* shPart= shG + H * D;              // 4*H*D (warp partials / scratch)
    float* shL   = shPart + 4 * H * D;       // MAXD*H logits->att
    float* shC   = shL + MAXD * H;           // MAXD
    int*   shE   = (int*)(shC + MAXD);       // MAXD
    float* shm   = (float*)(shE + MAXD);     // H
    float* shs   = shm + H;                  // H
    float* shred = shs + H;                  // 4*H

    const int tid  = threadIdx.x;
    const int lane = tid & 31;
    const int w    = tid >> 5;

    for (int i = tid; i < D * D; i += 128) shWv[i] = Wv[i];
    __syncthreads();

    for (int n = blockIdx.x; n < N_NODES; n += gridDim.x) {
        const int base = g_off[n];
        const int deg  = g_off[n + 1] - base;
        if (deg == 0) { g_h2[(size_t)n * D + tid] = 0.f; continue; }
        const bool small = (deg <= MAXD);

        #pragma unroll
        for (int h = 0; h < H; h++)
            shG[h * D + tid] = g_gk[((size_t)n * H + h) * D + tid];
        __syncthreads();

        // ---- pass A: logits + per-warp head max (prefetched) ----
        float lmax[H];
        #pragma unroll
        for (int h = 0; h < H; h++) lmax[h] = -1e30f;
        {
            int i = w;
            int e_nx = 0; float4 q_nx = make_float4(0,0,0,0);
            if (i < deg) {
                e_nx = g_eorder[base + i];
                q_nx = *(const float4*)&g_q[(size_t)e_nx * D + lane * 4];
            }
            while (i < deg) {
                const int e = e_nx; const float4 q4 = q_nx;
                const int i2 = i + 4;
                if (i2 < deg) {
                    e_nx = g_eorder[base + i2];
                    q_nx = *(const float4*)&g_q[(size_t)e_nx * D + lane * 4];
                }
                if (small && lane == 0) { shE[i] = e; shC[i] = g_C[e]; }
                #pragma unroll
                for (int h = 0; h < H; h++) {
                    const float4 g4 = *(const float4*)&shG[h * D + lane * 4];
                    float p = q4.x*g4.x + q4.y*g4.y + q4.z*g4.z + q4.w*g4.w;
                    #pragma unroll
                    for (int o = 16; o; o >>= 1)
                        p += __shfl_xor_sync(0xffffffffu, p, o);
                    p *= INV_SQRT_P;
                    if (small) { if (lane == h) shL[i * H + h] = p; }
                    else       { if (lane == h) g_logit[(size_t)e * H + h] = p; }
                    lmax[h] = fmaxf(lmax[h], p);
                }
                i = i2;
            }
        }
        if (lane == 0) {
            #pragma unroll
            for (int h = 0; h < H; h++) shred[w * H + h] = lmax[h];
        }
        __syncthreads();
        if (tid < H)
            shm[tid] = fmaxf(fmaxf(shred[tid], shred[H + tid]),
                             fmaxf(shred[2 * H + tid], shred[3 * H + tid]));
        __syncthreads();

        // ---- pass B: att = exp(l-m)*C in shL; s per head ----
        if (small) {
            float s = 0.f;
            const int hh = tid & 7;
            const float mh = shm[hh];
            for (int j = tid; j < deg * H; j += 128) {
                float val = __expf(shL[j] - mh) * shC[j >> 3];
                shL[j] = val;
                s += val;
            }
            shPart[tid] = s;
            __syncthreads();
            if (tid < H) {
                float tot = 0.f;
                #pragma unroll
                for (int k = 0; k < 16; k++) tot += shPart[tid + 8 * k];
                shs[tid] = 1.0f / tot;
            }
        } else {
            float s = 0.f;
            if (lane < H) {
                for (int i = w; i < deg; i += 4) {
                    const int e = g_eorder[base + i];
                    s += __expf(g_logit[(size_t)e * H + lane] - shm[lane]) * g_C[e];
                }
                shred[w * H + lane] = s;
            }
            __syncthreads();
            if (tid < H)
                shs[tid] = 1.0f / (shred[tid] + shred[H + tid] +
                                   shred[2 * H + tid] + shred[3 * H + tid]);
        }
        __syncthreads();

        // ---- pass C: per-warp Y accumulation (prefetched), no barriers ----
        float4 acc[H];
        #pragma unroll
        for (int h = 0; h < H; h++) acc[h] = make_float4(0,0,0,0);
        if (small) {
            int i = w;
            int e_nx = 0; float4 q_nx = make_float4(0,0,0,0);
            if (i < deg) {
                e_nx = shE[i];
                q_nx = *(const float4*)&g_q[(size_t)e_nx * D + lane * 4];
            }
            while (i < deg) {
                const float4 q4 = q_nx;
                const int ii = i;
                const int i2 = i + 4;
                if (i2 < deg) {
                    e_nx = shE[i2];
                    q_nx = *(const float4*)&g_q[(size_t)e_nx * D + lane * 4];
                }
                #pragma unroll
                for (int h = 0; h < H; h++) {
                    const float a = shL[ii * H + h];
                    acc[h].x += a * q4.x; acc[h].y += a * q4.y;
                    acc[h].z += a * q4.z; acc[h].w += a * q4.w;
                }
                i = i2;
            }
        } else {
            for (int i = w; i < deg; i += 4) {
                const int e = g_eorder[base + i];
                const float Ce = g_C[e];
                const float4 q4 = *(const float4*)&g_q[(size_t)e * D + lane * 4];
                #pragma unroll
                for (int h = 0; h < H; h++) {
                    const float a = __expf(g_logit[(size_t)e * H + h] - shm[h]) * Ce;
                    acc[h].x += a * q4.x; acc[h].y += a * q4.y;
                    acc[h].z += a * q4.z; acc[h].w += a * q4.w;
                }
            }
        }
        #pragma unroll
        for (int h = 0; h < H; h++)
            *(float4*)&shPart[w * H * D + h * D + lane * 4] = acc[h];
        __syncthreads();

        // reduce 4 warp partials, scale by sinv, into shG (= Y)
        #pragma unroll
        for (int k = 0; k < H; k++) {
            const int j = k * D + tid;
            float y = shPart[j] + shPart[H*D + j] + shPart[2*H*D + j] + shPart[3*H*D + j];
            shG[j] = y * shs[k];
        }
        __syncthreads();

        // h2[tid] = sum_d Y[tid/16, d] * Wv[d, tid]
        const int hh = tid >> 4;
        float hv = 0.f;
        #pragma unroll 16
        for (int d0 = 0; d0 < D; d0++) hv += shG[hh * D + d0] * shWv[d0 * D + tid];
        g_h2[(size_t)n * D + tid] = hv;
        __syncthreads();
    }
}

// ---------------- K8: m_agg = h2 @ Wo ----------------
__global__ void __launch_bounds__(128) k8_out(const float* __restrict__ Wo,
                                              float* __restrict__ outM) {
    extern __shared__ float sm[];
    float* shW = sm;
    float* shx = sm + D * D;
    const int tid = threadIdx.x;
    for (int i = tid; i < D * D; i += 128) shW[i] = Wo[i];
    __syncthreads();
    for (int n = blockIdx.x; n < N_NODES; n += gridDim.x) {
        shx[tid] = g_h2[(size_t)n * D + tid];
        __syncthreads();
        float acc = 0.f;
        #pragma unroll 16
        for (int k = 0; k < D; k++) acc += shx[k] * shW[k * D + tid];
        outM[(size_t)n * D + tid] = acc;
        __syncthreads();
    }
}

// ---------------- launch ----------------
extern "C" void kernel_launch(void* const* d_in, const int* in_sizes, int n_in,
                              void* d_out, int out_size) {
    const float* pos  = (const float*)d_in[0];
    const float* h1   = (const float*)d_in[1];
    const float* t    = (const float*)d_in[2];
    const float* fw   = (const float*)d_in[3];
    const float* fb   = (const float*)d_in[4];
    const float* ln_g = (const float*)d_in[5];
    const float* ln_b = (const float*)d_in[6];
    const float* Wq   = (const float*)d_in[7];
    const float* Wk   = (const float*)d_in[8];
    const float* Wv   = (const float*)d_in[9];
    const float* Wo   = (const float*)d_in[10];
    const int* src    = (const int*)d_in[11];
    const int* dst    = (const int*)d_in[12];
    const int* q_id   = (const int*)d_in[13];

    float* out  = (float*)d_out;
    float* outM = out;                              // m_agg [N,D]
    float* outW = out + (size_t)N_NODES * D;        // W     [E,D]

    const size_t sm_mat = (size_t)(D * D + D) * sizeof(float);
    const size_t sm_gk  = (size_t)(128 * 129 + 128) * sizeof(float);
    const size_t sm_k7  = (size_t)(D*D + H*D + 4*H*D + MAXD*H + MAXD + MAXD
                                   + H + H + 4*H) * sizeof(float);   // ~96.5 KB

    cudaFuncSetAttribute(k4_qv,   cudaFuncAttributeMaxDynamicSharedMemorySize, (int)sm_mat);
    cudaFuncSetAttribute(k5_gk,   cudaFuncAttributeMaxDynamicSharedMemorySize, (int)sm_gk);
    cudaFuncSetAttribute(k7_node, cudaFuncAttributeMaxDynamicSharedMemorySize, (int)sm_k7);
    cudaFuncSetAttribute(k8_out,  cudaFuncAttributeMaxDynamicSharedMemorySize, (int)sm_mat);

    k0_init<<<(N_NODES + 255) / 256, 256>>>();
    k1_edge<<<N_EDGES / 8, 128>>>(pos, h1, t, fw, fb, ln_g, ln_b, src, dst, outW);
    k2_scan<<<1, 256>>>();
    k3_scatter<<<256, 256>>>(src);
    k4_qv<<<444, 128, sm_mat>>>(Wq, q_id);
    k5_gk<<<444, 128, sm_gk>>>(Wk);
    k7_node<<<444, 128, sm_k7>>>(Wv);
    k8_out<<<444, 128, sm_mat>>>(Wo, outM);
}

// round 3
// speedup vs baseline: 1.3641x; 1.3480x over previous
#include <cuda_runtime.h>
#include <math.h>

#define N_NODES 20000
#define N_EDGES 320000
#define D 128
#define H 8
#define PH 16
#define G 64
#define LN_EPS 1e-5f
#define MAXD 256

#define WIDTH   (5.0f / 63.0f)
#define INV_W   (63.0f / 5.0f)
#define EXP_COEF (-0.5f * INV_W * INV_W)
#define PI_OVER_CUT 0.62831853071795864f
#define INV_SQRT_P 0.25f

// ---------------- scratch (device globals, no runtime allocation) ----------------
static __device__ __align__(16) float g_q[(size_t)N_EDGES * D];
static __device__ float g_C[N_EDGES];
static __device__ float g_logit[(size_t)N_EDGES * H];               // fallback (deg > MAXD)
static __device__ __align__(16) float g_qv[(size_t)N_NODES * D];
static __device__ __align__(16) float g_gk[(size_t)N_NODES * H * D];
static __device__ float g_h2[(size_t)N_NODES * D];
static __device__ int g_hist[N_NODES];
static __device__ int g_off[N_NODES + 1];
static __device__ int g_cursor[N_NODES];
static __device__ int g_eorder[N_EDGES];

// ---------------- K0 (split x3 so k1 is the 4th launch => ncu profiles k1) ----------------
__global__ void k0a_init() {
    int i = blockIdx.x * blockDim.x + threadIdx.x;
    if (i < 6667) g_hist[i] = 0;
}
__global__ void k0b_init() {
    int i = 6667 + blockIdx.x * blockDim.x + threadIdx.x;
    if (i < 13334) g_hist[i] = 0;
}
__global__ void k0c_init() {
    int i = 13334 + blockIdx.x * blockDim.x + threadIdx.x;
    if (i < N_NODES) g_hist[i] = 0;
}

// ---------------- K1: warp-per-edge, float4 columns, no barriers in edge loop ----------------
// block = 4 warps; warp w handles 16 consecutive edges; lane owns columns lane*4..lane*4+3.
__global__ void __launch_bounds__(128) k1_edge(
    const float* __restrict__ pos, const float* __restrict__ h1,
    const float* __restrict__ t,   const float* __restrict__ fw,
    const float* __restrict__ fb,  const float* __restrict__ ln_g,
    const float* __restrict__ ln_b,const int* __restrict__ src,
    const int* __restrict__ dst,   float* __restrict__ outW)
{
    __shared__ float4 sh_fw[G * 32];     // [g][lane], 32 KB
    const int tid  = threadIdx.x;
    const int lane = tid & 31;
    const int w    = tid >> 5;

    for (int i = tid; i < G * 32; i += 128) sh_fw[i] = ((const float4*)fw)[i];
    __syncthreads();

    float4 colsum = make_float4(0.f, 0.f, 0.f, 0.f);
    #pragma unroll
    for (int g = 0; g < G; g++) {
        const float4 w4 = sh_fw[g * 32 + lane];
        colsum.x += w4.x; colsum.y += w4.y; colsum.z += w4.z; colsum.w += w4.w;
    }
    const float4 fb4 = ((const float4*)fb)[lane];
    const float4 lg4 = ((const float4*)ln_g)[lane];
    const float4 lb4 = ((const float4*)ln_b)[lane];

    const int e0 = blockIdx.x * 64 + w * 16;
    #pragma unroll 1
    for (int ei = 0; ei < 16; ei++) {
        const int e = e0 + ei;
        const int s = src[e], dn = dst[e];
        const float dx = pos[dn*3+0] - pos[s*3+0];
        const float dy = pos[dn*3+1] - pos[s*3+1];
        const float dz = pos[dn*3+2] - pos[s*3+2];
        const float r  = sqrtf(dx*dx + dy*dy + dz*dz);
        const float C  = (r < 5.0f) ? 0.5f * (__cosf(r * PI_OVER_CUT) + 1.0f) : 0.0f;

        const int i0  = __float2int_rn(r * INV_W);
        const int glo = max(0, i0 - 6);
        const int ghi = min(G - 1, i0 + 6);
        const int nwin = ghi - glo + 1;           // <= 13
        float myf = 0.f;
        if (lane < nwin) {
            const float dr = r - (glo + lane) * WIDTH;
            myf = __expf(EXP_COEF * dr * dr);
        }

        float4 acc = make_float4(0.f, 0.f, 0.f, 0.f);
        for (int j = 0; j < nwin; j++) {
            const float fj = __shfl_sync(0xffffffffu, myf, j);
            const float4 w4 = sh_fw[(glo + j) * 32 + lane];
            acc.x += fj * w4.x; acc.y += fj * w4.y;
            acc.z += fj * w4.z; acc.w += fj * w4.w;
        }
        float4 W4;
        W4.x = (2.0f * acc.x - colsum.x + fb4.x) * C;
        W4.y = (2.0f * acc.y - colsum.y + fb4.y) * C;
        W4.z = (2.0f * acc.z - colsum.z + fb4.z) * C;
        W4.w = (2.0f * acc.w - colsum.w + fb4.w) * C;
        ((float4*)outW)[(size_t)e * 32 + lane] = W4;

        const float4 h4 = ((const float4*)h1)[(size_t)dn * 32 + lane];
        const float4 t4 = ((const float4*)t)[(size_t)e * 32 + lane];
        float4 v;
        v.x = W4.x * h4.x + t4.x; v.y = W4.y * h4.y + t4.y;
        v.z = W4.z * h4.z + t4.z; v.w = W4.w * h4.w + t4.w;

        float sm = v.x + v.y + v.z + v.w;
        float sq = v.x*v.x + v.y*v.y + v.z*v.z + v.w*v.w;
        #pragma unroll
        for (int o = 16; o; o >>= 1) {
            sm += __shfl_xor_sync(0xffffffffu, sm, o);
            sq += __shfl_xor_sync(0xffffffffu, sq, o);
        }
        const float mu  = sm * (1.0f / D);
        const float var = sq * (1.0f / D) - mu * mu;
        const float inv = rsqrtf(var + LN_EPS);
        float4 qo;
        qo.x = (v.x - mu) * inv * lg4.x + lb4.x;
        qo.y = (v.y - mu) * inv * lg4.y + lb4.y;
        qo.z = (v.z - mu) * inv * lg4.z + lb4.z;
        qo.w = (v.w - mu) * inv * lg4.w + lb4.w;
        ((float4*)g_q)[(size_t)e * 32 + lane] = qo;

        if (lane == 0) { g_C[e] = C; atomicAdd(&g_hist[s], 1); }
    }
}

// ---------------- K2: single-block exclusive scan of histogram ----------------
__global__ void k2_scan() {
    __shared__ int sh[256];
    const int tid = threadIdx.x;
    const int CH = (N_NODES + 255) / 256;
    const int lo = tid * CH;
    const int hi = min(lo + CH, N_NODES);
    int s = 0;
    for (int i = lo; i < hi; i++) s += g_hist[i];
    sh[tid] = s;
    __syncthreads();
    for (int off = 1; off < 256; off <<= 1) {
        int v = (tid >= off) ? sh[tid - off] : 0;
        __syncthreads();
        sh[tid] += v;
        __syncthreads();
    }
    int base = (tid == 0) ? 0 : sh[tid - 1];
    for (int i = lo; i < hi; i++) {
        int c = g_hist[i];
        g_off[i] = base;
        g_cursor[i] = base;
        base += c;
    }
    if (tid == 0) g_off[N_NODES] = N_EDGES;
}

// ---------------- K3: scatter edges into src-sorted order ----------------
__global__ void k3_scatter(const int* __restrict__ src) {
    for (int e = blockIdx.x * blockDim.x + threadIdx.x; e < N_EDGES;
         e += gridDim.x * blockDim.x) {
        int p = atomicAdd(&g_cursor[src[e]], 1);
        g_eorder[p] = e;
    }
}

// ---------------- K4: qv[n] = q[q_id[n]] @ Wq ----------------
__global__ void __launch_bounds__(128) k4_qv(const float* __restrict__ Wq,
                                             const int* __restrict__ q_id) {
    extern __shared__ float sm[];
    float* shW = sm;
    float* shx = sm + D * D;
    const int tid = threadIdx.x;
    for (int i = tid; i < D * D; i += 128) shW[i] = Wq[i];
    __syncthreads();
    for (int n = blockIdx.x; n < N_NODES; n += gridDim.x) {
        shx[tid] = g_q[(size_t)q_id[n] * D + tid];
        __syncthreads();
        float acc = 0.f;
        #pragma unroll 16
        for (int k = 0; k < D; k++) acc += shx[k] * shW[k * D + tid];
        g_qv[(size_t)n * D + tid] = acc;
        __syncthreads();
    }
}

// ---------------- K5: gk[n,h,d] = sum_p Wk[d, h*16+p] * qv[n, h*16+p] ----------------
__global__ void __launch_bounds__(128) k5_gk(const float* __restrict__ Wk) {
    extern __shared__ float sm[];
    float* shWT = sm;               // [j][d] transposed, stride 129
    float* shx  = sm + 128 * 129;
    const int tid = threadIdx.x;
    for (int i = tid; i < D * D; i += 128) {
        int dd = i >> 7, j = i & 127;
        shWT[j * 129 + dd] = Wk[i];
    }
    __syncthreads();
    for (int n = blockIdx.x; n < N_NODES; n += gridDim.x) {
        shx[tid] = g_qv[(size_t)n * D + tid];
        __syncthreads();
        #pragma unroll
        for (int h = 0; h < H; h++) {
            float acc = 0.f;
            #pragma unroll
            for (int p = 0; p < PH; p++) {
                int j = h * PH + p;
                acc += shWT[j * 129 + tid] * shx[j];
            }
            g_gk[((size_t)n * H + h) * D + tid] = acc;
        }
        __syncthreads();
    }
}

// ---------------- K7: per-node logits + softmax + Y + h2 = Y @ Wv ----------------
__global__ void __launch_bounds__(128) k7_node(const float* __restrict__ Wv) {
    extern __shared__ float sm[];
    float* shWv  = sm;                       // D*D
    float* shG   = shWv + D * D;             // H*D  (gk, then Y)
    float* shPart= shG + H * D;              // 4*H*D
    float* shL   = shPart + 4 * H * D;       // MAXD*H
    float* shC   = shL + MAXD * H;           // MAXD
    int*   shE   = (int*)(shC + MAXD);       // MAXD
    float* shm   = (float*)(shE + MAXD);     // H
    float* shs   = shm + H;                  // H
    float* shred = shs + H;                  // 4*H

    const int tid  = threadIdx.x;
    const int lane = tid & 31;
    const int w    = tid >> 5;

    for (int i = tid; i < D * D; i += 128) shWv[i] = Wv[i];
    __syncthreads();

    for (int n = blockIdx.x; n < N_NODES; n += gridDim.x) {
        const int base = g_off[n];
        const int deg  = g_off[n + 1] - base;
        if (deg == 0) { g_h2[(size_t)n * D + tid] = 0.f; continue; }
        const bool small = (deg <= MAXD);

        #pragma unroll
        for (int h = 0; h < H; h++)
            shG[h * D + tid] = g_gk[((size_t)n * H + h) * D + tid];
        if (small) {
            for (int i = tid; i < deg; i += 128) {
                const int e = g_eorder[base + i];
                shE[i] = e;
                shC[i] = g_C[e];
            }
        }
        __syncthreads();

        // ---- pass A: logits + per-warp head max (prefetched) ----
        float lmax[H];
        #pragma unroll
        for (int h = 0; h < H; h++) lmax[h] = -1e30f;
        {
            int i = w;
            int e_nx = 0; float4 q_nx = make_float4(0,0,0,0);
            if (i < deg) {
                e_nx = small ? shE[i] : g_eorder[base + i];
                q_nx = *(const float4*)&g_q[(size_t)e_nx * D + lane * 4];
            }
            while (i < deg) {
                const int e = e_nx; const float4 q4 = q_nx;
                const int i2 = i + 4;
                if (i2 < deg) {
                    e_nx = small ? shE[i2] : g_eorder[base + i2];
                    q_nx = *(const float4*)&g_q[(size_t)e_nx * D + lane * 4];
                }
                #pragma unroll
                for (int h = 0; h < H; h++) {
                    const float4 g4 = *(const float4*)&shG[h * D + lane * 4];
                    float p = q4.x*g4.x + q4.y*g4.y + q4.z*g4.z + q4.w*g4.w;
                    #pragma unroll
                    for (int o = 16; o; o >>= 1)
                        p += __shfl_xor_sync(0xffffffffu, p, o);
                    p *= INV_SQRT_P;
                    if (small) { if (lane == h) shL[i * H + h] = p; }
                    else       { if (lane == h) g_logit[(size_t)e * H + h] = p; }
                    lmax[h] = fmaxf(lmax[h], p);
                }
                i = i2;
            }
        }
        if (lane == 0) {
            #pragma unroll
            for (int h = 0; h < H; h++) shred[w * H + h] = lmax[h];
        }
        __syncthreads();
        if (tid < H)
            shm[tid] = fmaxf(fmaxf(shred[tid], shred[H + tid]),
                             fmaxf(shred[2 * H + tid], shred[3 * H + tid]));
        __syncthreads();

        // ---- pass B: att = exp(l-m)*C in shL; s per head ----
        if (small) {
            float s = 0.f;
            const int hh = tid & 7;
            const float mh = shm[hh];
            for (int j = tid; j < deg * H; j += 128) {
                float val = __expf(shL[j] - mh) * shC[j >> 3];
                shL[j] = val;
                s += val;
            }
            shPart[tid] = s;
            __syncthreads();
            if (tid < H) {
                float tot = 0.f;
                #pragma unroll
                for (int k = 0; k < 16; k++) tot += shPart[tid + 8 * k];
                shs[tid] = 1.0f / tot;
            }
        } else {
            float s = 0.f;
            if (lane < H) {
                for (int i = w; i < deg; i += 4) {
                    const int e = g_eorder[base + i];
                    s += __expf(g_logit[(size_t)e * H + lane] - shm[lane]) * g_C[e];
                }
                shred[w * H + lane] = s;
            }
            __syncthreads();
            if (tid < H)
                shs[tid] = 1.0f / (shred[tid] + shred[H + tid] +
                                   shred[2 * H + tid] + shred[3 * H + tid]);
        }
        __syncthreads();

        // ---- pass C: per-warp Y accumulation (prefetched), no barriers ----
        float4 acc[H];
        #pragma unroll
        for (int h = 0; h < H; h++) acc[h] = make_float4(0,0,0,0);
        if (small) {
            int i = w;
            int e_nx = 0; float4 q_nx = make_float4(0,0,0,0);
            if (i < deg) {
                e_nx = shE[i];
                q_nx = *(const float4*)&g_q[(size_t)e_nx * D + lane * 4];
            }
            while (i < deg) {
                const float4 q4 = q_nx;
                const int ii = i;
                const int i2 = i + 4;
                if (i2 < deg) {
                    e_nx = shE[i2];
                    q_nx = *(const float4*)&g_q[(size_t)e_nx * D + lane * 4];
                }
                #pragma unroll
                for (int h = 0; h < H; h++) {
                    const float a = shL[ii * H + h];
                    acc[h].x += a * q4.x; acc[h].y += a * q4.y;
                    acc[h].z += a * q4.z; acc[h].w += a * q4.w;
                }
                i = i2;
            }
        } else {
            for (int i = w; i < deg; i += 4) {
                const int e = g_eorder[base + i];
                const float Ce = g_C[e];
                const float4 q4 = *(const float4*)&g_q[(size_t)e * D + lane * 4];
                #pragma unroll
                for (int h = 0; h < H; h++) {
                    const float a = __expf(g_logit[(size_t)e * H + h] - shm[h]) * Ce;
                    acc[h].x += a * q4.x; acc[h].y += a * q4.y;
                    acc[h].z += a * q4.z; acc[h].w += a * q4.w;
                }
            }
        }
        #pragma unroll
        for (int h = 0; h < H; h++)
            *(float4*)&shPart[w * H * D + h * D + lane * 4] = acc[h];
        __syncthreads();

        #pragma unroll
        for (int k = 0; k < H; k++) {
            const int j = k * D + tid;
            float y = shPart[j] + shPart[H*D + j] + shPart[2*H*D + j] + shPart[3*H*D + j];
            shG[j] = y * shs[k];
        }
        __syncthreads();

        const int hh = tid >> 4;
        float hv = 0.f;
        #pragma unroll 16
        for (int d0 = 0; d0 < D; d0++) hv += shG[hh * D + d0] * shWv[d0 * D + tid];
        g_h2[(size_t)n * D + tid] = hv;
        __syncthreads();
    }
}

// ---------------- K8: m_agg = h2 @ Wo ----------------
__global__ void __launch_bounds__(128) k8_out(const float* __restrict__ Wo,
                                              float* __restrict__ outM) {
    extern __shared__ float sm[];
    float* shW = sm;
    float* shx = sm + D * D;
    const int tid = threadIdx.x;
    for (int i = tid; i < D * D; i += 128) shW[i] = Wo[i];
    __syncthreads();
    for (int n = blockIdx.x; n < N_NODES; n += gridDim.x) {
        shx[tid] = g_h2[(size_t)n * D + tid];
        __syncthreads();
        float acc = 0.f;
        #pragma unroll 16
        for (int k = 0; k < D; k++) acc += shx[k] * shW[k * D + tid];
        outM[(size_t)n * D + tid] = acc;
        __syncthreads();
    }
}

// ---------------- launch ----------------
extern "C" void kernel_launch(void* const* d_in, const int* in_sizes, int n_in,
                              void* d_out, int out_size) {
    const float* pos  = (const float*)d_in[0];
    const float* h1   = (const float*)d_in[1];
    const float* t    = (const float*)d_in[2];
    const float* fw   = (const float*)d_in[3];
    const float* fb   = (const float*)d_in[4];
    const float* ln_g = (const float*)d_in[5];
    const float* ln_b = (const float*)d_in[6];
    const float* Wq   = (const float*)d_in[7];
    const float* Wk   = (const float*)d_in[8];
    const float* Wv   = (const float*)d_in[9];
    const float* Wo   = (const float*)d_in[10];
    const int* src    = (const int*)d_in[11];
    const int* dst    = (const int*)d_in[12];
    const int* q_id   = (const int*)d_in[13];

    float* out  = (float*)d_out;
    float* outM = out;                              // m_agg [N,D]
    float* outW = out + (size_t)N_NODES * D;        // W     [E,D]

    const size_t sm_mat = (size_t)(D * D + D) * sizeof(float);
    const size_t sm_gk  = (size_t)(128 * 129 + 128) * sizeof(float);
    const size_t sm_k7  = (size_t)(D*D + H*D + 4*H*D + MAXD*H + MAXD + MAXD
                                   + H + H + 4*H) * sizeof(float);

    cudaFuncSetAttribute(k4_qv,   cudaFuncAttributeMaxDynamicSharedMemorySize, (int)sm_mat);
    cudaFuncSetAttribute(k5_gk,   cudaFuncAttributeMaxDynamicSharedMemorySize, (int)sm_gk);
    cudaFuncSetAttribute(k7_node, cudaFuncAttributeMaxDynamicSharedMemorySize, (int)sm_k7);
    cudaFuncSetAttribute(k8_out,  cudaFuncAttributeMaxDynamicSharedMemorySize, (int)sm_mat);

    // launch order chosen so k1_edge is the 4th launch (ncu profiles index 3)
    k0a_init<<<27, 256>>>();
    k0b_init<<<27, 256>>>();
    k0c_init<<<27, 256>>>();
    k1_edge<<<N_EDGES / 64, 128>>>(pos, h1, t, fw, fb, ln_g, ln_b, src, dst, outW);
    k2_scan<<<1, 256>>>();
    k3_scatter<<<256, 256>>>(src);
    k4_qv<<<444, 128, sm_mat>>>(Wq, q_id);
    k5_gk<<<444, 128, sm_gk>>>(Wk);
    k7_node<<<444, 128, sm_k7>>>(Wv);
    k8_out<<<444, 128, sm_mat>>>(Wo, outM);
}

// round 4
// speedup vs baseline: 1.7058x; 1.2505x over previous
#include <cuda_runtime.h>
#include <math.h>

#define N_NODES 20000
#define N_EDGES 320000
#define D 128
#define H 8
#define PH 16
#define G 64
#define LN_EPS 1e-5f

#define WIDTH   (5.0f / 63.0f)
#define INV_W   (63.0f / 5.0f)
#define EXP_COEF (-0.5f * INV_W * INV_W)
#define PI_OVER_CUT 0.62831853071795864f
#define INV_SQRT_P 0.25f

// ---------------- scratch (device globals; zero-initialized at load) ----------------
static __device__ __align__(16) float g_q[(size_t)N_EDGES * D];     // SORTED by src
static __device__ float g_C[N_EDGES];                               // SORTED by src
static __device__ __align__(16) float g_gk[(size_t)N_NODES * H * D];
static __device__ float g_h2[(size_t)N_NODES * D];
static __device__ int g_hist[N_NODES];        // zeroed by k2 after use (and by static init)
static __device__ int g_off[N_NODES + 1];
static __device__ int g_cursor[N_NODES];
static __device__ int g_pos[N_EDGES];         // orig edge id -> sorted position

// ---------------- KH: histogram of src ----------------
__global__ void kh_hist(const int* __restrict__ src) {
    for (int e = blockIdx.x * blockDim.x + threadIdx.x; e < N_EDGES;
         e += gridDim.x * blockDim.x)
        atomicAdd(&g_hist[src[e]], 1);
}

// ---------------- K2: single-block scan; also re-zeroes hist for next call ----------------
__global__ void k2_scan() {
    __shared__ int sh[256];
    const int tid = threadIdx.x;
    const int CH = (N_NODES + 255) / 256;
    const int lo = tid * CH;
    const int hi = min(lo + CH, N_NODES);
    int s = 0;
    for (int i = lo; i < hi; i++) s += g_hist[i];
    sh[tid] = s;
    __syncthreads();
    for (int off = 1; off < 256; off <<= 1) {
        int v = (tid >= off) ? sh[tid - off] : 0;
        __syncthreads();
        sh[tid] += v;
        __syncthreads();
    }
    int base = (tid == 0) ? 0 : sh[tid - 1];
    for (int i = lo; i < hi; i++) {
        int c = g_hist[i];
        g_off[i] = base;
        g_cursor[i] = base;
        g_hist[i] = 0;            // ready for next call
        base += c;
    }
    if (tid == 0) g_off[N_NODES] = N_EDGES;
}

// ---------------- K1: warp-per-edge; writes W (orig order) + q,C (sorted order) ----------------
__global__ void __launch_bounds__(128) k1_edge(
    const float* __restrict__ pos, const float* __restrict__ h1,
    const float* __restrict__ t,   const float* __restrict__ fw,
    const float* __restrict__ fb,  const float* __restrict__ ln_g,
    const float* __restrict__ ln_b,const int* __restrict__ src,
    const int* __restrict__ dst,   float* __restrict__ outW)
{
    __shared__ float4 sh_fw[G * 32];     // [g][lane], 32 KB
    const int tid  = threadIdx.x;
    const int lane = tid & 31;
    const int w    = tid >> 5;

    for (int i = tid; i < G * 32; i += 128) sh_fw[i] = ((const float4*)fw)[i];
    __syncthreads();

    float4 colsum = make_float4(0.f, 0.f, 0.f, 0.f);
    #pragma unroll
    for (int g = 0; g < G; g++) {
        const float4 w4 = sh_fw[g * 32 + lane];
        colsum.x += w4.x; colsum.y += w4.y; colsum.z += w4.z; colsum.w += w4.w;
    }
    const float4 fb4 = ((const float4*)fb)[lane];
    const float4 lg4 = ((const float4*)ln_g)[lane];
    const float4 lb4 = ((const float4*)ln_b)[lane];

    const int e0 = blockIdx.x * 64 + w * 16;
    #pragma unroll 1
    for (int ei = 0; ei < 16; ei++) {
        const int e = e0 + ei;
        const int s = src[e], dn = dst[e];

        // sorted position for this edge (lane 0 claims, broadcast)
        int p = 0;
        if (lane == 0) p = atomicAdd(&g_cursor[s], 1);
        p = __shfl_sync(0xffffffffu, p, 0);

        const float dx = pos[dn*3+0] - pos[s*3+0];
        const float dy = pos[dn*3+1] - pos[s*3+1];
        const float dz = pos[dn*3+2] - pos[s*3+2];
        const float r  = sqrtf(dx*dx + dy*dy + dz*dz);
        const float C  = (r < 5.0f) ? 0.5f * (__cosf(r * PI_OVER_CUT) + 1.0f) : 0.0f;

        const int i0  = __float2int_rn(r * INV_W);
        const int glo = max(0, i0 - 6);
        const int ghi = min(G - 1, i0 + 6);
        const int nwin = ghi - glo + 1;           // <= 13
        float myf = 0.f;
        if (lane < nwin) {
            const float dr = r - (glo + lane) * WIDTH;
            myf = __expf(EXP_COEF * dr * dr);
        }

        float4 acc = make_float4(0.f, 0.f, 0.f, 0.f);
        for (int j = 0; j < nwin; j++) {
            const float fj = __shfl_sync(0xffffffffu, myf, j);
            const float4 w4 = sh_fw[(glo + j) * 32 + lane];
            acc.x += fj * w4.x; acc.y += fj * w4.y;
            acc.z += fj * w4.z; acc.w += fj * w4.w;
        }
        float4 W4;
        W4.x = (2.0f * acc.x - colsum.x + fb4.x) * C;
        W4.y = (2.0f * acc.y - colsum.y + fb4.y) * C;
        W4.z = (2.0f * acc.z - colsum.z + fb4.z) * C;
        W4.w = (2.0f * acc.w - colsum.w + fb4.w) * C;
        ((float4*)outW)[(size_t)e * 32 + lane] = W4;

        const float4 h4 = ((const float4*)h1)[(size_t)dn * 32 + lane];
        const float4 t4 = ((const float4*)t)[(size_t)e * 32 + lane];
        float4 v;
        v.x = W4.x * h4.x + t4.x; v.y = W4.y * h4.y + t4.y;
        v.z = W4.z * h4.z + t4.z; v.w = W4.w * h4.w + t4.w;

        float sm = v.x + v.y + v.z + v.w;
        float sq = v.x*v.x + v.y*v.y + v.z*v.z + v.w*v.w;
        #pragma unroll
        for (int o = 16; o; o >>= 1) {
            sm += __shfl_xor_sync(0xffffffffu, sm, o);
            sq += __shfl_xor_sync(0xffffffffu, sq, o);
        }
        const float mu  = sm * (1.0f / D);
        const float var = sq * (1.0f / D) - mu * mu;
        const float inv = rsqrtf(var + LN_EPS);
        float4 qo;
        qo.x = (v.x - mu) * inv * lg4.x + lb4.x;
        qo.y = (v.y - mu) * inv * lg4.y + lb4.y;
        qo.z = (v.z - mu) * inv * lg4.z + lb4.z;
        qo.w = (v.w - mu) * inv * lg4.w + lb4.w;
        ((float4*)g_q)[(size_t)p * 32 + lane] = qo;     // sorted position

        if (lane == 0) { g_C[p] = C; g_pos[e] = p; }
    }
}

// ---------------- K45: qv = q[pos(q_id[n])] @ Wq (smem only), gk = per-head Wk contraction ----------------
__global__ void __launch_bounds__(256) k45_gk(
    const float* __restrict__ Wq, const float* __restrict__ Wk,
    const int* __restrict__ q_id)
{
    extern __shared__ float sm[];
    float* shWq  = sm;                    // 128*128
    float* shWkT = shWq + D * D;          // [j][d] stride 129
    float* shx   = shWkT + 128 * 129;     // 128
    float* shp   = shx + D;               // 256
    float* shqv  = shp + 256;             // 128
    const int tid = threadIdx.x;

    for (int i = tid; i < D * D; i += 256) shWq[i] = Wq[i];
    for (int i = tid; i < D * D; i += 256) {
        int dd = i >> 7, j = i & 127;
        shWkT[j * 129 + dd] = Wk[i];
    }
    __syncthreads();

    for (int n = blockIdx.x; n < N_NODES; n += gridDim.x) {
        const int p = g_pos[q_id[n]];
        if (tid < 128) shx[tid] = g_q[(size_t)p * D + tid];
        __syncthreads();
        {   // split-k qv
            const int j = tid & 127;
            const int k0 = (tid >> 7) * 64;
            float a = 0.f;
            #pragma unroll 16
            for (int k = 0; k < 64; k++) a += shx[k0 + k] * shWq[(k0 + k) * D + j];
            shp[tid] = a;
        }
        __syncthreads();
        if (tid < 128) shqv[tid] = shp[tid] + shp[tid + 128];
        __syncthreads();
        #pragma unroll
        for (int rep = 0; rep < 4; rep++) {
            const int idx = rep * 256 + tid;
            const int h = idx >> 7, dd = idx & 127;
            float a = 0.f;
            #pragma unroll
            for (int pp = 0; pp < PH; pp++) {
                const int j = h * PH + pp;
                a += shWkT[j * 129 + dd] * shqv[j];
            }
            g_gk[((size_t)n * H + h) * D + dd] = a;
        }
        __syncthreads();
    }
}

// ---------------- K7: single-pass online softmax + Y + h2 = Y @ Wv ----------------
__global__ void __launch_bounds__(128) k7_node(const float* __restrict__ Wv) {
    extern __shared__ float sm[];
    float* shWv = sm;                    // D*D        64 KB
    float* shG  = shWv + D * D;          // H*D  (gk, then normalized Y)
    float* shP  = shG + H * D;           // 4*H*D warp Y partials
    float* shMS = shP + 4 * H * D;       // [w][16]: m(0..7), s(8..15)
    float* shSC = shMS + 64;             // [w][8] merge scales
    float* shs  = shSC + 32;             // [8] 1/ssum
    const int tid  = threadIdx.x;
    const int lane = tid & 31;
    const int w    = tid >> 5;

    for (int i = tid; i < D * D; i += 128) shWv[i] = Wv[i];
    __syncthreads();

    for (int n = blockIdx.x; n < N_NODES; n += gridDim.x) {
        const int base = g_off[n];
        const int deg  = g_off[n + 1] - base;
        if (deg == 0) { g_h2[(size_t)n * D + tid] = 0.f; continue; }

        #pragma unroll
        for (int h = 0; h < H; h++)
            shG[h * D + tid] = g_gk[((size_t)n * H + h) * D + tid];
        __syncthreads();
        float4 g4[H];
        #pragma unroll
        for (int h = 0; h < H; h++) g4[h] = *(const float4*)&shG[h * D + lane * 4];

        float m[H], s[H]; float4 Y[H];
        #pragma unroll
        for (int h = 0; h < H; h++) {
            m[h] = -1e30f; s[h] = 0.f; Y[h] = make_float4(0,0,0,0);
        }

        for (int i = w; i < deg; i += 4) {
            const float4 q4 = ((const float4*)g_q)[(size_t)(base + i) * 32 + lane];
            const float Ce  = g_C[base + i];
            #pragma unroll
            for (int h = 0; h < H; h++) {
                float pq = q4.x*g4[h].x + q4.y*g4[h].y + q4.z*g4[h].z + q4.w*g4[h].w;
                #pragma unroll
                for (int o = 16; o; o >>= 1)
                    pq += __shfl_xor_sync(0xffffffffu, pq, o);
                pq *= INV_SQRT_P;
                const float nm = fmaxf(m[h], pq);
                const float sc = __expf(m[h] - nm);
                const float ww = __expf(pq - nm) * Ce;
                s[h] = s[h] * sc + ww;
                Y[h].x = Y[h].x * sc + ww * q4.x;
                Y[h].y = Y[h].y * sc + ww * q4.y;
                Y[h].z = Y[h].z * sc + ww * q4.z;
                Y[h].w = Y[h].w * sc + ww * q4.w;
                m[h] = nm;
            }
        }

        #pragma unroll
        for (int h = 0; h < H; h++)
            *(float4*)&shP[((size_t)w * H + h) * D + lane * 4] = Y[h];
        if (lane < H) { shMS[w * 16 + lane] = m[lane]; shMS[w * 16 + 8 + lane] = s[lane]; }
        __syncthreads();

        if (tid < H) {
            float mm = fmaxf(fmaxf(shMS[tid], shMS[16 + tid]),
                             fmaxf(shMS[32 + tid], shMS[48 + tid]));
            float ssum = 0.f;
            #pragma unroll
            for (int w4 = 0; w4 < 4; w4++) {
                const float e = __expf(shMS[w4 * 16 + tid] - mm);
                shSC[w4 * 8 + tid] = e;
                ssum += shMS[w4 * 16 + 8 + tid] * e;
            }
            shs[tid] = 1.0f / ssum;
        }
        __syncthreads();

        #pragma unroll
        for (int h = 0; h < H; h++) {
            const float y = shP[(0*H + h) * D + tid] * shSC[h]
                          + shP[(1*H + h) * D + tid] * shSC[8 + h]
                          + shP[(2*H + h) * D + tid] * shSC[16 + h]
                          + shP[(3*H + h) * D + tid] * shSC[24 + h];
            shG[h * D + tid] = y * shs[h];
        }
        __syncthreads();

        const int hh = tid >> 4;
        float hv = 0.f;
        #pragma unroll 16
        for (int d0 = 0; d0 < D; d0++) hv += shG[hh * D + d0] * shWv[d0 * D + tid];
        g_h2[(size_t)n * D + tid] = hv;
        __syncthreads();
    }
}

// ---------------- K8: m_agg = h2 @ Wo ----------------
__global__ void __launch_bounds__(128) k8_out(const float* __restrict__ Wo,
                                              float* __restrict__ outM) {
    extern __shared__ float sm[];
    float* shW = sm;
    float* shx = sm + D * D;
    const int tid = threadIdx.x;
    for (int i = tid; i < D * D; i += 128) shW[i] = Wo[i];
    __syncthreads();
    for (int n = blockIdx.x; n < N_NODES; n += gridDim.x) {
        shx[tid] = g_h2[(size_t)n * D + tid];
        __syncthreads();
        float acc = 0.f;
        #pragma unroll 16
        for (int k = 0; k < D; k++) acc += shx[k] * shW[k * D + tid];
        outM[(size_t)n * D + tid] = acc;
        __syncthreads();
    }
}

// ---------------- launch ----------------
extern "C" void kernel_launch(void* const* d_in, const int* in_sizes, int n_in,
                              void* d_out, int out_size) {
    const float* pos  = (const float*)d_in[0];
    const float* h1   = (const float*)d_in[1];
    const float* t    = (const float*)d_in[2];
    const float* fw   = (const float*)d_in[3];
    const float* fb   = (const float*)d_in[4];
    const float* ln_g = (const float*)d_in[5];
    const float* ln_b = (const float*)d_in[6];
    const float* Wq   = (const float*)d_in[7];
    const float* Wk   = (const float*)d_in[8];
    const float* Wv   = (const float*)d_in[9];
    const float* Wo   = (const float*)d_in[10];
    const int* src    = (const int*)d_in[11];
    const int* dst    = (const int*)d_in[12];
    const int* q_id   = (const int*)d_in[13];

    float* out  = (float*)d_out;
    float* outM = out;                              // m_agg [N,D]
    float* outW = out + (size_t)N_NODES * D;        // W     [E,D]

    const size_t sm_k45 = (size_t)(D*D + 128*129 + D + 256 + D) * sizeof(float); // ~133.6 KB
    const size_t sm_k7  = (size_t)(D*D + H*D + 4*H*D + 64 + 32 + 8) * sizeof(float); // ~86.4 KB
    const size_t sm_mat = (size_t)(D * D + D) * sizeof(float);

    cudaFuncSetAttribute(k45_gk,  cudaFuncAttributeMaxDynamicSharedMemorySize, (int)sm_k45);
    cudaFuncSetAttribute(k7_node, cudaFuncAttributeMaxDynamicSharedMemorySize, (int)sm_k7);
    cudaFuncSetAttribute(k8_out,  cudaFuncAttributeMaxDynamicSharedMemorySize, (int)sm_mat);

    kh_hist<<<256, 256>>>(src);                                       // 1
    k2_scan<<<1, 256>>>();                                            // 2
    k1_edge<<<N_EDGES / 64, 128>>>(pos, h1, t, fw, fb, ln_g, ln_b,
                                   src, dst, outW);                   // 3
    k45_gk<<<148, 256, sm_k45>>>(Wq, Wk, q_id);                       // 4  <-- profiled
    k7_node<<<296, 128, sm_k7>>>(Wv);                                 // 5
    k8_out<<<444, 128, sm_mat>>>(Wo, outM);                           // 6
}

// round 5
// speedup vs baseline: 2.2946x; 1.3452x over previous
#include <cuda_runtime.h>
#include <math.h>

#define N_NODES 20000
#define N_EDGES 320000
#define D 128
#define H 8
#define G 64
#define LN_EPS 1e-5f
#define MAXD 512

#define WIDTH   (5.0f / 63.0f)
#define INV_W   (63.0f / 5.0f)
#define EXP_COEF (-0.5f * INV_W * INV_W)
#define PI_OVER_CUT 0.62831853071795864f
#define INV_SQRT_P 0.25f

// ---------------- scratch ----------------
static __device__ __align__(16) float g_q[(size_t)N_EDGES * D];     // SORTED by src
static __device__ float g_C[N_EDGES];                               // SORTED by src
static __device__ __align__(16) float g_qv[(size_t)N_NODES * D];
static __device__ __align__(16) float g_gk[(size_t)N_NODES * H * D];
static __device__ __align__(16) float g_h2[(size_t)N_NODES * D];
static __device__ int g_hist[N_NODES];
static __device__ int g_off[N_NODES + 1];
static __device__ int g_cursor[N_NODES];
static __device__ int g_pos[N_EDGES];

// ---------------- KH: histogram of src ----------------
__global__ void kh_hist(const int* __restrict__ src) {
    for (int e = blockIdx.x * blockDim.x + threadIdx.x; e < N_EDGES;
         e += gridDim.x * blockDim.x)
        atomicAdd(&g_hist[src[e]], 1);
}

// ---------------- K2: single-block scan; re-zeroes hist ----------------
__global__ void k2_scan() {
    __shared__ int sh[256];
    const int tid = threadIdx.x;
    const int CH = (N_NODES + 255) / 256;
    const int lo = tid * CH;
    const int hi = min(lo + CH, N_NODES);
    int s = 0;
    for (int i = lo; i < hi; i++) s += g_hist[i];
    sh[tid] = s;
    __syncthreads();
    for (int off = 1; off < 256; off <<= 1) {
        int v = (tid >= off) ? sh[tid - off] : 0;
        __syncthreads();
        sh[tid] += v;
        __syncthreads();
    }
    int base = (tid == 0) ? 0 : sh[tid - 1];
    for (int i = lo; i < hi; i++) {
        int c = g_hist[i];
        g_off[i] = base;
        g_cursor[i] = base;
        g_hist[i] = 0;
        base += c;
    }
    if (tid == 0) g_off[N_NODES] = N_EDGES;
}

// ---------------- K1: warp-per-edge; W (orig order) + q,C (sorted order) ----------------
__global__ void __launch_bounds__(128) k1_edge(
    const float* __restrict__ pos, const float* __restrict__ h1,
    const float* __restrict__ t,   const float* __restrict__ fw,
    const float* __restrict__ fb,  const float* __restrict__ ln_g,
    const float* __restrict__ ln_b,const int* __restrict__ src,
    const int* __restrict__ dst,   float* __restrict__ outW)
{
    __shared__ float4 sh_fw[G * 32];
    const int tid  = threadIdx.x;
    const int lane = tid & 31;
    const int w    = tid >> 5;

    for (int i = tid; i < G * 32; i += 128) sh_fw[i] = ((const float4*)fw)[i];
    __syncthreads();

    float4 colsum = make_float4(0.f, 0.f, 0.f, 0.f);
    #pragma unroll
    for (int g = 0; g < G; g++) {
        const float4 w4 = sh_fw[g * 32 + lane];
        colsum.x += w4.x; colsum.y += w4.y; colsum.z += w4.z; colsum.w += w4.w;
    }
    const float4 fb4 = ((const float4*)fb)[lane];
    const float4 lg4 = ((const float4*)ln_g)[lane];
    const float4 lb4 = ((const float4*)ln_b)[lane];

    const int e0 = blockIdx.x * 64 + w * 16;
    #pragma unroll 1
    for (int ei = 0; ei < 16; ei++) {
        const int e = e0 + ei;
        const int s = src[e], dn = dst[e];

        int p = 0;
        if (lane == 0) p = atomicAdd(&g_cursor[s], 1);
        p = __shfl_sync(0xffffffffu, p, 0);

        const float dx = pos[dn*3+0] - pos[s*3+0];
        const float dy = pos[dn*3+1] - pos[s*3+1];
        const float dz = pos[dn*3+2] - pos[s*3+2];
        const float r  = sqrtf(dx*dx + dy*dy + dz*dz);
        const float C  = (r < 5.0f) ? 0.5f * (__cosf(r * PI_OVER_CUT) + 1.0f) : 0.0f;

        const int i0  = __float2int_rn(r * INV_W);
        const int glo = max(0, i0 - 6);
        const int ghi = min(G - 1, i0 + 6);
        const int nwin = ghi - glo + 1;
        float myf = 0.f;
        if (lane < nwin) {
            const float dr = r - (glo + lane) * WIDTH;
            myf = __expf(EXP_COEF * dr * dr);
        }

        float4 acc = make_float4(0.f, 0.f, 0.f, 0.f);
        for (int j = 0; j < nwin; j++) {
            const float fj = __shfl_sync(0xffffffffu, myf, j);
            const float4 w4 = sh_fw[(glo + j) * 32 + lane];
            acc.x += fj * w4.x; acc.y += fj * w4.y;
            acc.z += fj * w4.z; acc.w += fj * w4.w;
        }
        float4 W4;
        W4.x = (2.0f * acc.x - colsum.x + fb4.x) * C;
        W4.y = (2.0f * acc.y - colsum.y + fb4.y) * C;
        W4.z = (2.0f * acc.z - colsum.z + fb4.z) * C;
        W4.w = (2.0f * acc.w - colsum.w + fb4.w) * C;
        ((float4*)outW)[(size_t)e * 32 + lane] = W4;

        const float4 h4 = ((const float4*)h1)[(size_t)dn * 32 + lane];
        const float4 t4 = ((const float4*)t)[(size_t)e * 32 + lane];
        float4 v;
        v.x = W4.x * h4.x + t4.x; v.y = W4.y * h4.y + t4.y;
        v.z = W4.z * h4.z + t4.z; v.w = W4.w * h4.w + t4.w;

        float sm = v.x + v.y + v.z + v.w;
        float sq = v.x*v.x + v.y*v.y + v.z*v.z + v.w*v.w;
        #pragma unroll
        for (int o = 16; o; o >>= 1) {
            sm += __shfl_xor_sync(0xffffffffu, sm, o);
            sq += __shfl_xor_sync(0xffffffffu, sq, o);
        }
        const float mu  = sm * (1.0f / D);
        const float var = sq * (1.0f / D) - mu * mu;
        const float inv = rsqrtf(var + LN_EPS);
        float4 qo;
        qo.x = (v.x - mu) * inv * lg4.x + lb4.x;
        qo.y = (v.y - mu) * inv * lg4.y + lb4.y;
        qo.z = (v.z - mu) * inv * lg4.z + lb4.z;
        qo.w = (v.w - mu) * inv * lg4.w + lb4.w;
        ((float4*)g_q)[(size_t)p * 32 + lane] = qo;

        if (lane == 0) { g_C[p] = C; g_pos[e] = p; }
    }
}

// ---------------- K4: tiled gather-GEMM  qv = qsel @ Wq  (32 rows/tile) ----------------
__global__ void __launch_bounds__(256) k4_qv(const float* __restrict__ Wq,
                                             const int* __restrict__ q_id) {
    extern __shared__ float sm[];
    float* shW = sm;                       // 16384
    float* shq = shW + 16384;              // 4096
    int*   shIdx = (int*)(shq + 4096);     // 32
    const int tid = threadIdx.x;
    const int tx = tid & 31, ty = tid >> 5;

    for (int i = tid; i < D * D; i += 256) shW[i] = Wq[i];

    for (int tile = blockIdx.x; tile < N_NODES / 32; tile += gridDim.x) {
        const int n0 = tile * 32;
        __syncthreads();
        if (tid < 32) shIdx[tid] = g_pos[q_id[n0 + tid]];
        __syncthreads();
        for (int i = tid; i < 1024; i += 256)
            ((float4*)shq)[i] = ((const float4*)g_q)[(size_t)shIdx[i >> 5] * 32 + (i & 31)];
        __syncthreads();

        float4 a0 = make_float4(0,0,0,0), a1 = a0, a2 = a0, a3 = a0;
        const float* q0 = shq + (ty * 4) * D;
        #pragma unroll 4
        for (int k = 0; k < D; k++) {
            const float4 wv = ((const float4*)shW)[k * 32 + tx];
            const float b0 = q0[k], b1 = q0[D + k], b2 = q0[2*D + k], b3 = q0[3*D + k];
            a0.x += b0*wv.x; a0.y += b0*wv.y; a0.z += b0*wv.z; a0.w += b0*wv.w;
            a1.x += b1*wv.x; a1.y += b1*wv.y; a1.z += b1*wv.z; a1.w += b1*wv.w;
            a2.x += b2*wv.x; a2.y += b2*wv.y; a2.z += b2*wv.z; a2.w += b2*wv.w;
            a3.x += b3*wv.x; a3.y += b3*wv.y; a3.z += b3*wv.z; a3.w += b3*wv.w;
        }
        ((float4*)g_qv)[(size_t)(n0 + ty*4 + 0) * 32 + tx] = a0;
        ((float4*)g_qv)[(size_t)(n0 + ty*4 + 1) * 32 + tx] = a1;
        ((float4*)g_qv)[(size_t)(n0 + ty*4 + 2) * 32 + tx] = a2;
        ((float4*)g_qv)[(size_t)(n0 + ty*4 + 3) * 32 + tx] = a3;
    }
}

// ---------------- K5: tiled gk[n,h,d] = sum_p Wk[d,h*16+p]*qv[n,h*16+p] ----------------
__global__ void __launch_bounds__(256) k5_gk(const float* __restrict__ Wk) {
    extern __shared__ float sm[];
    float* shWT = sm;                      // 128*132 = 16896 (transposed, padded)
    float* shqv = shWT + 16896;            // 4096
    const int tid = threadIdx.x;
    const int h = tid >> 5, c = tid & 31;

    for (int i = tid; i < D * D; i += 256) {
        const int d = i >> 7, j = i & 127;
        shWT[j * 132 + d] = Wk[i];
    }
    const float4* wrow = (const float4*)shWT;   // row stride 33 float4

    for (int tile = blockIdx.x; tile < N_NODES / 32; tile += gridDim.x) {
        const int n0 = tile * 32;
        __syncthreads();
        for (int i = tid; i < 1024; i += 256)
            ((float4*)shqv)[i] = ((const float4*)g_qv)[(size_t)n0 * 32 + i];
        __syncthreads();
        #pragma unroll 1
        for (int n = 0; n < 32; n++) {
            const float* qn = shqv + n * D + h * 16;
            float4 acc = make_float4(0,0,0,0);
            #pragma unroll
            for (int p = 0; p < 16; p++) {
                const float a = qn[p];
                const float4 w4 = wrow[(h*16 + p) * 33 + c];
                acc.x += a*w4.x; acc.y += a*w4.y; acc.z += a*w4.z; acc.w += a*w4.w;
            }
            ((float4*)g_gk)[((size_t)(n0 + n) * H + h) * 32 + c] = acc;
        }
    }
}

// ---------------- K7: two-pass smem-logit attention + h2 = Y @ Wv ----------------
__global__ void __launch_bounds__(128) k7_node(const float* __restrict__ Wv) {
    extern __shared__ float sm[];
    float* shWv = sm;                 // 16384
    float* shG  = shWv + 16384;       // 1024 (gk, then Y)
    float* shP  = shG + 1024;         // 4096 warp partials
    float* shL  = shP + 4096;         // 4096 = MAXD*8 logits->att
    float* shC  = shL + 4096;         // 512
    float* shm  = shC + 512;          // 8
    float* shs  = shm + 8;            // 8
    float* shred= shs + 8;            // 128

    const int tid  = threadIdx.x;
    const int lane = tid & 31;
    const int w    = tid >> 5;
    const int myh  = lane >> 2;

    for (int i = tid; i < D * D; i += 128) shWv[i] = Wv[i];
    __syncthreads();

    for (int n = blockIdx.x; n < N_NODES; n += gridDim.x) {
        const int base = g_off[n];
        const int deg  = g_off[n + 1] - base;
        if (deg == 0) { g_h2[(size_t)n * D + tid] = 0.f; continue; }

        #pragma unroll
        for (int h = 0; h < H; h++)
            shG[h * D + tid] = g_gk[((size_t)n * H + h) * D + tid];
        for (int i = tid; i < deg && i < MAXD; i += 128)
            shC[i] = g_C[base + i];
        __syncthreads();

        float4 g4[H];
        #pragma unroll
        for (int h = 0; h < H; h++) g4[h] = *(const float4*)&shG[h * D + lane * 4];

        if (deg <= MAXD) {
            // ---- pass A: logits (26-shfl reduction) + own-head max ----
            float mown = -1e30f;
            {
                int i = w;
                float4 qn = make_float4(0,0,0,0);
                if (i < deg) qn = ((const float4*)g_q)[(size_t)(base + i) * 32 + lane];
                while (i < deg) {
                    const float4 q4 = qn;
                    const int ii = i, i2 = i + 4;
                    if (i2 < deg) qn = ((const float4*)g_q)[(size_t)(base + i2) * 32 + lane];
                    float pr0 = q4.x*g4[0].x + q4.y*g4[0].y + q4.z*g4[0].z + q4.w*g4[0].w;
                    float pr1 = q4.x*g4[1].x + q4.y*g4[1].y + q4.z*g4[1].z + q4.w*g4[1].w;
                    float pr2 = q4.x*g4[2].x + q4.y*g4[2].y + q4.z*g4[2].z + q4.w*g4[2].w;
                    float pr3 = q4.x*g4[3].x + q4.y*g4[3].y + q4.z*g4[3].z + q4.w*g4[3].w;
                    float pr4 = q4.x*g4[4].x + q4.y*g4[4].y + q4.z*g4[4].z + q4.w*g4[4].w;
                    float pr5 = q4.x*g4[5].x + q4.y*g4[5].y + q4.z*g4[5].z + q4.w*g4[5].w;
                    float pr6 = q4.x*g4[6].x + q4.y*g4[6].y + q4.z*g4[6].z + q4.w*g4[6].w;
                    float pr7 = q4.x*g4[7].x + q4.y*g4[7].y + q4.z*g4[7].z + q4.w*g4[7].w;
                    #pragma unroll
                    for (int off = 16; off >= 4; off >>= 1) {
                        pr0 += __shfl_xor_sync(0xffffffffu, pr0, off);
                        pr1 += __shfl_xor_sync(0xffffffffu, pr1, off);
                        pr2 += __shfl_xor_sync(0xffffffffu, pr2, off);
                        pr3 += __shfl_xor_sync(0xffffffffu, pr3, off);
                        pr4 += __shfl_xor_sync(0xffffffffu, pr4, off);
                        pr5 += __shfl_xor_sync(0xffffffffu, pr5, off);
                        pr6 += __shfl_xor_sync(0xffffffffu, pr6, off);
                        pr7 += __shfl_xor_sync(0xffffffffu, pr7, off);
                    }
                    const float t0 = (lane & 4) ? pr1 : pr0;
                    const float t1 = (lane & 4) ? pr3 : pr2;
                    const float t2 = (lane & 4) ? pr5 : pr4;
                    const float t3 = (lane & 4) ? pr7 : pr6;
                    const float u0 = (lane & 8) ? t1 : t0;
                    const float u1 = (lane & 8) ? t3 : t2;
                    float x = (lane & 16) ? u1 : u0;
                    x += __shfl_xor_sync(0xffffffffu, x, 2);
                    x += __shfl_xor_sync(0xffffffffu, x, 1);
                    x *= INV_SQRT_P;
                    if ((lane & 3) == 0) shL[ii * 8 + myh] = x;
                    mown = fmaxf(mown, x);
                    i = i2;
                }
            }
            shred[w * 32 + lane] = mown;
            __syncthreads();
            if (tid < H) {
                float mm = -1e30f;
                #pragma unroll
                for (int ww = 0; ww < 4; ww++)
                    #pragma unroll
                    for (int k = 0; k < 4; k++)
                        mm = fmaxf(mm, shred[ww * 32 + tid * 4 + k]);
                shm[tid] = mm;
            }
            __syncthreads();

            // ---- pass B: att = exp(l-m)*C; per-head sums ----
            float sp = 0.f;
            const float mh = shm[tid & 7];
            for (int j = tid; j < deg * 8; j += 128) {
                const float v = __expf(shL[j] - mh) * shC[j >> 3];
                shL[j] = v;
                sp += v;
            }
            shred[tid] = sp;
            __syncthreads();
            if (tid < H) {
                float s = 0.f;
                #pragma unroll
                for (int k = 0; k < 16; k++) s += shred[tid + 8 * k];
                shs[tid] = 1.0f / s;
            }
            __syncthreads();

            // ---- pass C: Y accumulation (shfl/exp-free) ----
            float4 Y[H];
            #pragma unroll
            for (int h = 0; h < H; h++) Y[h] = make_float4(0,0,0,0);
            {
                int i = w;
                float4 qn = make_float4(0,0,0,0);
                if (i < deg) qn = ((const float4*)g_q)[(size_t)(base + i) * 32 + lane];
                while (i < deg) {
                    const float4 q4 = qn;
                    const int ii = i, i2 = i + 4;
                    if (i2 < deg) qn = ((const float4*)g_q)[(size_t)(base + i2) * 32 + lane];
                    #pragma unroll
                    for (int h = 0; h < H; h++) {
                        const float a = shL[ii * 8 + h];
                        Y[h].x += a * q4.x; Y[h].y += a * q4.y;
                        Y[h].z += a * q4.z; Y[h].w += a * q4.w;
                    }
                    i = i2;
                }
            }
            #pragma unroll
            for (int h = 0; h < H; h++)
                *(float4*)&shP[(w * H + h) * D + lane * 4] = Y[h];
            __syncthreads();
            #pragma unroll
            for (int h = 0; h < H; h++) {
                const int j = h * D + tid;
                const float y = shP[j] + shP[1024 + j] + shP[2048 + j] + shP[3072 + j];
                shG[j] = y * shs[h];
            }
            __syncthreads();
        } else {
            // ---- fallback: flash online softmax (practically unreachable) ----
            float m[H], s[H]; float4 Y[H];
            #pragma unroll
            for (int h = 0; h < H; h++) { m[h] = -1e30f; s[h] = 0.f; Y[h] = make_float4(0,0,0,0); }
            for (int i = w; i < deg; i += 4) {
                const float4 q4 = ((const float4*)g_q)[(size_t)(base + i) * 32 + lane];
                const float Ce = g_C[base + i];
                #pragma unroll
                for (int h = 0; h < H; h++) {
                    float pq = q4.x*g4[h].x + q4.y*g4[h].y + q4.z*g4[h].z + q4.w*g4[h].w;
                    #pragma unroll
                    for (int o = 16; o; o >>= 1) pq += __shfl_xor_sync(0xffffffffu, pq, o);
                    pq *= INV_SQRT_P;
                    const float nm = fmaxf(m[h], pq);
                    const float sc = __expf(m[h] - nm);
                    const float ww = __expf(pq - nm) * Ce;
                    s[h] = s[h] * sc + ww;
                    Y[h].x = Y[h].x * sc + ww * q4.x;
                    Y[h].y = Y[h].y * sc + ww * q4.y;
                    Y[h].z = Y[h].z * sc + ww * q4.z;
                    Y[h].w = Y[h].w * sc + ww * q4.w;
                    m[h] = nm;
                }
            }
            #pragma unroll
            for (int h = 0; h < H; h++) {
                *(float4*)&shP[(w * H + h) * D + lane * 4] = Y[h];
                if (lane == h) { shred[w * 16 + h] = m[h]; shred[w * 16 + 8 + h] = s[h]; }
            }
            __syncthreads();
            if (tid < H) {
                float mm = fmaxf(fmaxf(shred[tid], shred[16 + tid]),
                                 fmaxf(shred[32 + tid], shred[48 + tid]));
                float ssum = 0.f;
                #pragma unroll
                for (int w4 = 0; w4 < 4; w4++) {
                    const float e = __expf(shred[w4 * 16 + tid] - mm);
                    shred[64 + w4 * 8 + tid] = e;
                    ssum += shred[w4 * 16 + 8 + tid] * e;
                }
                shs[tid] = 1.0f / ssum;
            }
            __syncthreads();
            #pragma unroll
            for (int h = 0; h < H; h++) {
                const float y = shP[(0*H + h) * D + tid] * shred[64 + h]
                              + shP[(1*H + h) * D + tid] * shred[64 + 8 + h]
                              + shP[(2*H + h) * D + tid] * shred[64 + 16 + h]
                              + shP[(3*H + h) * D + tid] * shred[64 + 24 + h];
                shG[h * D + tid] = y * shs[h];
            }
            __syncthreads();
        }

        // epilogue: h2[j] = sum_d Y[j/16, d] * Wv[d, j]
        const int hh = tid >> 4;
        float hv = 0.f;
        #pragma unroll 16
        for (int d0 = 0; d0 < D; d0++) hv += shG[hh * D + d0] * shWv[d0 * D + tid];
        g_h2[(size_t)n * D + tid] = hv;
        __syncthreads();
    }
}

// ---------------- K8: tiled m_agg = h2 @ Wo ----------------
__global__ void __launch_bounds__(256) k8_out(const float* __restrict__ Wo,
                                              float* __restrict__ outM) {
    extern __shared__ float sm[];
    float* shW = sm;             // 16384
    float* shq = shW + 16384;    // 4096
    const int tid = threadIdx.x;
    const int tx = tid & 31, ty = tid >> 5;

    for (int i = tid; i < D * D; i += 256) shW[i] = Wo[i];

    for (int tile = blockIdx.x; tile < N_NODES / 32; tile += gridDim.x) {
        const int n0 = tile * 32;
        __syncthreads();
        for (int i = tid; i < 1024; i += 256)
            ((float4*)shq)[i] = ((const float4*)g_h2)[(size_t)n0 * 32 + i];
        __syncthreads();

        float4 a0 = make_float4(0,0,0,0), a1 = a0, a2 = a0, a3 = a0;
        const float* q0 = shq + (ty * 4) * D;
        #pragma unroll 4
        for (int k = 0; k < D; k++) {
            const float4 wv = ((const float4*)shW)[k * 32 + tx];
            const float b0 = q0[k], b1 = q0[D + k], b2 = q0[2*D + k], b3 = q0[3*D + k];
            a0.x += b0*wv.x; a0.y += b0*wv.y; a0.z += b0*wv.z; a0.w += b0*wv.w;
            a1.x += b1*wv.x; a1.y += b1*wv.y; a1.z += b1*wv.z; a1.w += b1*wv.w;
            a2.x += b2*wv.x; a2.y += b2*wv.y; a2.z += b2*wv.z; a2.w += b2*wv.w;
            a3.x += b3*wv.x; a3.y += b3*wv.y; a3.z += b3*wv.z; a3.w += b3*wv.w;
        }
        ((float4*)outM)[(size_t)(n0 + ty*4 + 0) * 32 + tx] = a0;
        ((float4*)outM)[(size_t)(n0 + ty*4 + 1) * 32 + tx] = a1;
        ((float4*)outM)[(size_t)(n0 + ty*4 + 2) * 32 + tx] = a2;
        ((float4*)outM)[(size_t)(n0 + ty*4 + 3) * 32 + tx] = a3;
    }
}

// ---------------- launch ----------------
extern "C" void kernel_launch(void* const* d_in, const int* in_sizes, int n_in,
                              void* d_out, int out_size) {
    const float* pos  = (const float*)d_in[0];
    const float* h1   = (const float*)d_in[1];
    const float* t    = (const float*)d_in[2];
    const float* fw   = (const float*)d_in[3];
    const float* fb   = (const float*)d_in[4];
    const float* ln_g = (const float*)d_in[5];
    const float* ln_b = (const float*)d_in[6];
    const float* Wq   = (const float*)d_in[7];
    const float* Wk   = (const float*)d_in[8];
    const float* Wv   = (const float*)d_in[9];
    const float* Wo   = (const float*)d_in[10];
    const int* src    = (const int*)d_in[11];
    const int* dst    = (const int*)d_in[12];
    const int* q_id   = (const int*)d_in[13];

    float* out  = (float*)d_out;
    float* outM = out;                              // m_agg [N,D]
    float* outW = out + (size_t)N_NODES * D;        // W     [E,D]

    const size_t sm_k4 = (16384 + 4096) * sizeof(float) + 32 * sizeof(int);   // ~82 KB
    const size_t sm_k5 = (16896 + 4096) * sizeof(float);                       // ~84 KB
    const size_t sm_k7 = (16384 + 1024 + 4096 + 4096 + 512 + 8 + 8 + 128) * sizeof(float); // ~105 KB
    const size_t sm_k8 = (16384 + 4096) * sizeof(float);                       // 80 KB

    cudaFuncSetAttribute(k4_qv,   cudaFuncAttributeMaxDynamicSharedMemorySize, (int)sm_k4);
    cudaFuncSetAttribute(k5_gk,   cudaFuncAttributeMaxDynamicSharedMemorySize, (int)sm_k5);
    cudaFuncSetAttribute(k7_node, cudaFuncAttributeMaxDynamicSharedMemorySize, (int)sm_k7);
    cudaFuncSetAttribute(k8_out,  cudaFuncAttributeMaxDynamicSharedMemorySize, (int)sm_k8);

    kh_hist<<<256, 256>>>(src);                                       // 0
    k2_scan<<<1, 256>>>();                                            // 1
    k1_edge<<<N_EDGES / 64, 128>>>(pos, h1, t, fw, fb, ln_g, ln_b,
                                   src, dst, outW);                   // 2
    k4_qv<<<296, 256, sm_k4>>>(Wq, q_id);                             // 3  <-- profiled
    k5_gk<<<296, 256, sm_k5>>>(Wk);                                   // 4
    k7_node<<<296, 128, sm_k7>>>(Wv);                                 // 5
    k8_out<<<296, 256, sm_k8>>>(Wo, outM);                            // 6
}

// round 6
// speedup vs baseline: 2.3125x; 1.0078x over previous
#include <cuda_runtime.h>
#include <math.h>

#define N_NODES 20000
#define N_EDGES 320000
#define D 128
#define H 8
#define G 64
#define LN_EPS 1e-5f
#define MAXD 128

#define WIDTH   (5.0f / 63.0f)
#define INV_W   (63.0f / 5.0f)
#define EXP_COEF (-0.5f * INV_W * INV_W)
#define PI_OVER_CUT 0.62831853071795864f
#define INV_SQRT_P 0.25f

// ---------------- scratch ----------------
static __device__ __align__(16) float g_q[(size_t)N_EDGES * D];     // SORTED by src
static __device__ float g_C[N_EDGES];                               // SORTED by src
static __device__ __align__(16) float g_gk[(size_t)N_NODES * H * D];
static __device__ __align__(16) float g_h2[(size_t)N_NODES * D];
static __device__ int g_hist[N_NODES];
static __device__ int g_off[N_NODES + 1];
static __device__ int g_cursor[N_NODES];
static __device__ int g_pos[N_EDGES];
static __device__ int g_done;

// ---------------- KA: fused histogram + scan (one launch) ----------------
__global__ void __launch_bounds__(256) ka_histscan(const int* __restrict__ src) {
    // phase 1: grid-wide histogram
    for (int e = blockIdx.x * blockDim.x + threadIdx.x; e < N_EDGES;
         e += gridDim.x * blockDim.x)
        atomicAdd(&g_hist[src[e]], 1);
    __threadfence();
    __syncthreads();
    if (threadIdx.x == 0) atomicAdd(&g_done, 1);

    // phase 2: block 0 waits for all blocks, then scans
    if (blockIdx.x != 0) return;
    if (threadIdx.x == 0) {
        while (*((volatile int*)&g_done) < (int)gridDim.x) { }
    }
    __syncthreads();
    __threadfence();

    __shared__ int sh[256];
    const int tid = threadIdx.x;
    const int CH = (N_NODES + 255) / 256;
    const int lo = tid * CH;
    const int hi = min(lo + CH, N_NODES);
    int s = 0;
    for (int i = lo; i < hi; i++) s += g_hist[i];
    sh[tid] = s;
    __syncthreads();
    for (int off = 1; off < 256; off <<= 1) {
        int v = (tid >= off) ? sh[tid - off] : 0;
        __syncthreads();
        sh[tid] += v;
        __syncthreads();
    }
    int base = (tid == 0) ? 0 : sh[tid - 1];
    for (int i = lo; i < hi; i++) {
        int c = g_hist[i];
        g_off[i] = base;
        g_cursor[i] = base;
        g_hist[i] = 0;                 // ready for next replay
        base += c;
    }
    __syncthreads();
    if (tid == 0) { g_off[N_NODES] = N_EDGES; g_done = 0; }
}

// ---------------- K1: warp-per-edge; W (orig order) + q,C (sorted order) ----------------
__global__ void __launch_bounds__(128) k1_edge(
    const float* __restrict__ pos, const float* __restrict__ h1,
    const float* __restrict__ t,   const float* __restrict__ fw,
    const float* __restrict__ fb,  const float* __restrict__ ln_g,
    const float* __restrict__ ln_b,const int* __restrict__ src,
    const int* __restrict__ dst,   float* __restrict__ outW)
{
    __shared__ float4 sh_fw[G * 32];
    const int tid  = threadIdx.x;
    const int lane = tid & 31;
    const int w    = tid >> 5;

    for (int i = tid; i < G * 32; i += 128) sh_fw[i] = ((const float4*)fw)[i];
    __syncthreads();

    float4 colsum = make_float4(0.f, 0.f, 0.f, 0.f);
    #pragma unroll
    for (int g = 0; g < G; g++) {
        const float4 w4 = sh_fw[g * 32 + lane];
        colsum.x += w4.x; colsum.y += w4.y; colsum.z += w4.z; colsum.w += w4.w;
    }
    const float4 fb4 = ((const float4*)fb)[lane];
    const float4 lg4 = ((const float4*)ln_g)[lane];
    const float4 lb4 = ((const float4*)ln_b)[lane];

    const int e0 = blockIdx.x * 64 + w * 16;
    #pragma unroll 1
    for (int ei = 0; ei < 16; ei++) {
        const int e = e0 + ei;
        const int s = src[e], dn = dst[e];

        int p = 0;
        if (lane == 0) p = atomicAdd(&g_cursor[s], 1);
        p = __shfl_sync(0xffffffffu, p, 0);

        const float dx = pos[dn*3+0] - pos[s*3+0];
        const float dy = pos[dn*3+1] - pos[s*3+1];
        const float dz = pos[dn*3+2] - pos[s*3+2];
        const float r  = sqrtf(dx*dx + dy*dy + dz*dz);
        const float C  = (r < 5.0f) ? 0.5f * (__cosf(r * PI_OVER_CUT) + 1.0f) : 0.0f;

        const int i0  = __float2int_rn(r * INV_W);
        const int glo = max(0, i0 - 6);
        const int ghi = min(G - 1, i0 + 6);
        const int nwin = ghi - glo + 1;
        float myf = 0.f;
        if (lane < nwin) {
            const float dr = r - (glo + lane) * WIDTH;
            myf = __expf(EXP_COEF * dr * dr);
        }

        float4 acc = make_float4(0.f, 0.f, 0.f, 0.f);
        for (int j = 0; j < nwin; j++) {
            const float fj = __shfl_sync(0xffffffffu, myf, j);
            const float4 w4 = sh_fw[(glo + j) * 32 + lane];
            acc.x += fj * w4.x; acc.y += fj * w4.y;
            acc.z += fj * w4.z; acc.w += fj * w4.w;
        }
        float4 W4;
        W4.x = (2.0f * acc.x - colsum.x + fb4.x) * C;
        W4.y = (2.0f * acc.y - colsum.y + fb4.y) * C;
        W4.z = (2.0f * acc.z - colsum.z + fb4.z) * C;
        W4.w = (2.0f * acc.w - colsum.w + fb4.w) * C;
        ((float4*)outW)[(size_t)e * 32 + lane] = W4;

        const float4 h4 = ((const float4*)h1)[(size_t)dn * 32 + lane];
        const float4 t4 = ((const float4*)t)[(size_t)e * 32 + lane];
        float4 v;
        v.x = W4.x * h4.x + t4.x; v.y = W4.y * h4.y + t4.y;
        v.z = W4.z * h4.z + t4.z; v.w = W4.w * h4.w + t4.w;

        float sm = v.x + v.y + v.z + v.w;
        float sq = v.x*v.x + v.y*v.y + v.z*v.z + v.w*v.w;
        #pragma unroll
        for (int o = 16; o; o >>= 1) {
            sm += __shfl_xor_sync(0xffffffffu, sm, o);
            sq += __shfl_xor_sync(0xffffffffu, sq, o);
        }
        const float mu  = sm * (1.0f / D);
        const float var = sq * (1.0f / D) - mu * mu;
        const float inv = rsqrtf(var + LN_EPS);
        float4 qo;
        qo.x = (v.x - mu) * inv * lg4.x + lb4.x;
        qo.y = (v.y - mu) * inv * lg4.y + lb4.y;
        qo.z = (v.z - mu) * inv * lg4.z + lb4.z;
        qo.w = (v.w - mu) * inv * lg4.w + lb4.w;
        ((float4*)g_q)[(size_t)p * 32 + lane] = qo;

        if (lane == 0) { g_C[p] = C; g_pos[e] = p; }
    }
}

// ---------------- K45: qv (smem-resident) then gk, tiled 32 nodes ----------------
__global__ void __launch_bounds__(256) k45_gk(
    const float* __restrict__ Wq, const float* __restrict__ Wk,
    const int* __restrict__ q_id)
{
    extern __shared__ float sm[];
    float* shWq  = sm;                    // 16384
    float* shWkT = shWq + 16384;          // 128*132 = 16896 (transposed, padded)
    float* shq   = shWkT + 16896;         // 4096
    float* shqv  = shq + 4096;            // 4096
    int*   shIdx = (int*)(shqv + 4096);   // 32
    const int tid = threadIdx.x;
    const int tx = tid & 31, ty = tid >> 5;

    for (int i = tid; i < D * D; i += 256) shWq[i] = Wq[i];
    for (int i = tid; i < D * D; i += 256) {
        const int d = i >> 7, j = i & 127;
        shWkT[j * 132 + d] = Wk[i];
    }
    const float4* wrow = (const float4*)shWkT;   // row stride 33 float4

    for (int tile = blockIdx.x; tile < N_NODES / 32; tile += gridDim.x) {
        const int n0 = tile * 32;
        __syncthreads();
        if (tid < 32) shIdx[tid] = g_pos[q_id[n0 + tid]];
        __syncthreads();
        for (int i = tid; i < 1024; i += 256)
            ((float4*)shq)[i] = ((const float4*)g_q)[(size_t)shIdx[i >> 5] * 32 + (i & 31)];
        __syncthreads();

        {   // qv = shq @ Wq  (each thread 4 rows x 4 cols)
            float4 a0 = make_float4(0,0,0,0), a1 = a0, a2 = a0, a3 = a0;
            const float* q0 = shq + (ty * 4) * D;
            #pragma unroll 4
            for (int k = 0; k < D; k++) {
                const float4 wv = ((const float4*)shWq)[k * 32 + tx];
                const float b0 = q0[k], b1 = q0[D + k], b2 = q0[2*D + k], b3 = q0[3*D + k];
                a0.x += b0*wv.x; a0.y += b0*wv.y; a0.z += b0*wv.z; a0.w += b0*wv.w;
                a1.x += b1*wv.x; a1.y += b1*wv.y; a1.z += b1*wv.z; a1.w += b1*wv.w;
                a2.x += b2*wv.x; a2.y += b2*wv.y; a2.z += b2*wv.z; a2.w += b2*wv.w;
                a3.x += b3*wv.x; a3.y += b3*wv.y; a3.z += b3*wv.z; a3.w += b3*wv.w;
            }
            ((float4*)shqv)[(ty*4 + 0) * 32 + tx] = a0;
            ((float4*)shqv)[(ty*4 + 1) * 32 + tx] = a1;
            ((float4*)shqv)[(ty*4 + 2) * 32 + tx] = a2;
            ((float4*)shqv)[(ty*4 + 3) * 32 + tx] = a3;
        }
        __syncthreads();

        {   // gk[n,h,:] = sum_p qv[n,h*16+p] * WkT[h*16+p, :]
            const int h = ty, c = tx;
            #pragma unroll 1
            for (int n = 0; n < 32; n++) {
                const float* qn = shqv + n * D + h * 16;
                float4 acc = make_float4(0,0,0,0);
                #pragma unroll
                for (int p = 0; p < 16; p++) {
                    const float a = qn[p];
                    const float4 w4 = wrow[(h*16 + p) * 33 + c];
                    acc.x += a*w4.x; acc.y += a*w4.y; acc.z += a*w4.z; acc.w += a*w4.w;
                }
                ((float4*)g_gk)[((size_t)(n0 + n) * H + h) * 32 + c] = acc;
            }
        }
    }
}

// ---------------- K7: two-pass smem-logit attention + h2 = Y @ Wv ----------------
__global__ void __launch_bounds__(128) k7_node(const float* __restrict__ Wv) {
    extern __shared__ float sm[];
    float* shWv = sm;                 // 16384
    float* shG  = shWv + 16384;       // 1024 (gk, then Y)
    float* shP  = shG + 1024;         // 4096 warp partials
    float* shL  = shP + 4096;         // 1024 = MAXD*8 logits->att
    float* shC  = shL + 1024;         // 128
    float* shm  = shC + MAXD;         // 8
    float* shs  = shm + 8;            // 8
    float* shred= shs + 8;            // 128

    const int tid  = threadIdx.x;
    const int lane = tid & 31;
    const int w    = tid >> 5;
    const int myh  = lane >> 2;

    for (int i = tid; i < D * D; i += 128) shWv[i] = Wv[i];
    __syncthreads();

    for (int n = blockIdx.x; n < N_NODES; n += gridDim.x) {
        const int base = g_off[n];
        const int deg  = g_off[n + 1] - base;
        if (deg == 0) { g_h2[(size_t)n * D + tid] = 0.f; continue; }

        #pragma unroll
        for (int h = 0; h < H; h++)
            shG[h * D + tid] = g_gk[((size_t)n * H + h) * D + tid];
        if (tid < deg && tid < MAXD) shC[tid] = g_C[base + tid];
        __syncthreads();

        float4 g4[H];
        #pragma unroll
        for (int h = 0; h < H; h++) g4[h] = *(const float4*)&shG[h * D + lane * 4];

        if (deg <= MAXD) {
            // ---- pass A: logits (26-shfl reduction) + own-head max ----
            float mown = -1e30f;
            {
                int i = w;
                float4 qn = make_float4(0,0,0,0);
                if (i < deg) qn = ((const float4*)g_q)[(size_t)(base + i) * 32 + lane];
                while (i < deg) {
                    const float4 q4 = qn;
                    const int ii = i, i2 = i + 4;
                    if (i2 < deg) qn = ((const float4*)g_q)[(size_t)(base + i2) * 32 + lane];
                    float pr0 = q4.x*g4[0].x + q4.y*g4[0].y + q4.z*g4[0].z + q4.w*g4[0].w;
                    float pr1 = q4.x*g4[1].x + q4.y*g4[1].y + q4.z*g4[1].z + q4.w*g4[1].w;
                    float pr2 = q4.x*g4[2].x + q4.y*g4[2].y + q4.z*g4[2].z + q4.w*g4[2].w;
                    float pr3 = q4.x*g4[3].x + q4.y*g4[3].y + q4.z*g4[3].z + q4.w*g4[3].w;
                    float pr4 = q4.x*g4[4].x + q4.y*g4[4].y + q4.z*g4[4].z + q4.w*g4[4].w;
                    float pr5 = q4.x*g4[5].x + q4.y*g4[5].y + q4.z*g4[5].z + q4.w*g4[5].w;
                    float pr6 = q4.x*g4[6].x + q4.y*g4[6].y + q4.z*g4[6].z + q4.w*g4[6].w;
                    float pr7 = q4.x*g4[7].x + q4.y*g4[7].y + q4.z*g4[7].z + q4.w*g4[7].w;
                    #pragma unroll
                    for (int off = 16; off >= 4; off >>= 1) {
                        pr0 += __shfl_xor_sync(0xffffffffu, pr0, off);
                        pr1 += __shfl_xor_sync(0xffffffffu, pr1, off);
                        pr2 += __shfl_xor_sync(0xffffffffu, pr2, off);
                        pr3 += __shfl_xor_sync(0xffffffffu, pr3, off);
                        pr4 += __shfl_xor_sync(0xffffffffu, pr4, off);
                        pr5 += __shfl_xor_sync(0xffffffffu, pr5, off);
                        pr6 += __shfl_xor_sync(0xffffffffu, pr6, off);
                        pr7 += __shfl_xor_sync(0xffffffffu, pr7, off);
                    }
                    const float t0 = (lane & 4) ? pr1 : pr0;
                    const float t1 = (lane & 4) ? pr3 : pr2;
                    const float t2 = (lane & 4) ? pr5 : pr4;
                    const float t3 = (lane & 4) ? pr7 : pr6;
                    const float u0 = (lane & 8) ? t1 : t0;
                    const float u1 = (lane & 8) ? t3 : t2;
                    float x = (lane & 16) ? u1 : u0;
                    x += __shfl_xor_sync(0xffffffffu, x, 2);
                    x += __shfl_xor_sync(0xffffffffu, x, 1);
                    x *= INV_SQRT_P;
                    if ((lane & 3) == 0) shL[ii * 8 + myh] = x;
                    mown = fmaxf(mown, x);
                    i = i2;
                }
            }
            shred[w * 32 + lane] = mown;
            __syncthreads();
            if (tid < H) {
                float mm = -1e30f;
                #pragma unroll
                for (int ww = 0; ww < 4; ww++)
                    #pragma unroll
                    for (int k = 0; k < 4; k++)
                        mm = fmaxf(mm, shred[ww * 32 + tid * 4 + k]);
                shm[tid] = mm;
            }
            __syncthreads();

            // ---- pass B: att = exp(l-m)*C; per-head sums ----
            float sp = 0.f;
            const float mh = shm[tid & 7];
            for (int j = tid; j < deg * 8; j += 128) {
                const float v = __expf(shL[j] - mh) * shC[j >> 3];
                shL[j] = v;
                sp += v;
            }
            shred[tid] = sp;
            __syncthreads();
            if (tid < H) {
                float s = 0.f;
                #pragma unroll
                for (int k = 0; k < 16; k++) s += shred[tid + 8 * k];
                shs[tid] = 1.0f / s;
            }
            __syncthreads();

            // ---- pass C: Y accumulation (shfl/exp-free) ----
            float4 Y[H];
            #pragma unroll
            for (int h = 0; h < H; h++) Y[h] = make_float4(0,0,0,0);
            {
                int i = w;
                float4 qn = make_float4(0,0,0,0);
                if (i < deg) qn = ((const float4*)g_q)[(size_t)(base + i) * 32 + lane];
                while (i < deg) {
                    const float4 q4 = qn;
                    const int ii = i, i2 = i + 4;
                    if (i2 < deg) qn = ((const float4*)g_q)[(size_t)(base + i2) * 32 + lane];
                    #pragma unroll
                    for (int h = 0; h < H; h++) {
                        const float a = shL[ii * 8 + h];
                        Y[h].x += a * q4.x; Y[h].y += a * q4.y;
                        Y[h].z += a * q4.z; Y[h].w += a * q4.w;
                    }
                    i = i2;
                }
            }
            #pragma unroll
            for (int h = 0; h < H; h++)
                *(float4*)&shP[(w * H + h) * D + lane * 4] = Y[h];
            __syncthreads();
            #pragma unroll
            for (int h = 0; h < H; h++) {
                const int j = h * D + tid;
                const float y = shP[j] + shP[1024 + j] + shP[2048 + j] + shP[3072 + j];
                shG[j] = y * shs[h];
            }
            __syncthreads();
        } else {
            // ---- fallback: flash online softmax (rare) ----
            float m[H], s[H]; float4 Y[H];
            #pragma unroll
            for (int h = 0; h < H; h++) { m[h] = -1e30f; s[h] = 0.f; Y[h] = make_float4(0,0,0,0); }
            for (int i = w; i < deg; i += 4) {
                const float4 q4 = ((const float4*)g_q)[(size_t)(base + i) * 32 + lane];
                const float Ce = g_C[base + i];
                #pragma unroll
                for (int h = 0; h < H; h++) {
                    float pq = q4.x*g4[h].x + q4.y*g4[h].y + q4.z*g4[h].z + q4.w*g4[h].w;
                    #pragma unroll
                    for (int o = 16; o; o >>= 1) pq += __shfl_xor_sync(0xffffffffu, pq, o);
                    pq *= INV_SQRT_P;
                    const float nm = fmaxf(m[h], pq);
                    const float sc = __expf(m[h] - nm);
                    const float ww = __expf(pq - nm) * Ce;
                    s[h] = s[h] * sc + ww;
                    Y[h].x = Y[h].x * sc + ww * q4.x;
                    Y[h].y = Y[h].y * sc + ww * q4.y;
                    Y[h].z = Y[h].z * sc + ww * q4.z;
                    Y[h].w = Y[h].w * sc + ww * q4.w;
                    m[h] = nm;
                }
            }
            #pragma unroll
            for (int h = 0; h < H; h++) {
                *(float4*)&shP[(w * H + h) * D + lane * 4] = Y[h];
                if (lane == h) { shred[w * 16 + h] = m[h]; shred[w * 16 + 8 + h] = s[h]; }
            }
            __syncthreads();
            if (tid < H) {
                float mm = fmaxf(fmaxf(shred[tid], shred[16 + tid]),
                                 fmaxf(shred[32 + tid], shred[48 + tid]));
                float ssum = 0.f;
                #pragma unroll
                for (int w4 = 0; w4 < 4; w4++) {
                    const float e = __expf(shred[w4 * 16 + tid] - mm);
                    shred[64 + w4 * 8 + tid] = e;
                    ssum += shred[w4 * 16 + 8 + tid] * e;
                }
                shs[tid] = 1.0f / ssum;
            }
            __syncthreads();
            #pragma unroll
            for (int h = 0; h < H; h++) {
                const float y = shP[(0*H + h) * D + tid] * shred[64 + h]
                              + shP[(1*H + h) * D + tid] * shred[64 + 8 + h]
                              + shP[(2*H + h) * D + tid] * shred[64 + 16 + h]
                              + shP[(3*H + h) * D + tid] * shred[64 + 24 + h];
                shG[h * D + tid] = y * shs[h];
            }
            __syncthreads();
        }

        // epilogue: h2[j] = sum_d Y[j/16, d] * Wv[d, j]
        const int hh = tid >> 4;
        float hv = 0.f;
        #pragma unroll 16
        for (int d0 = 0; d0 < D; d0++) hv += shG[hh * D + d0] * shWv[d0 * D + tid];
        g_h2[(size_t)n * D + tid] = hv;
        __syncthreads();
    }
}

// ---------------- K8: tiled m_agg = h2 @ Wo ----------------
__global__ void __launch_bounds__(256) k8_out(const float* __restrict__ Wo,
                                              float* __restrict__ outM) {
    extern __shared__ float sm[];
    float* shW = sm;             // 16384
    float* shq = shW + 16384;    // 4096
    const int tid = threadIdx.x;
    const int tx = tid & 31, ty = tid >> 5;

    for (int i = tid; i < D * D; i += 256) shW[i] = Wo[i];

    for (int tile = blockIdx.x; tile < N_NODES / 32; tile += gridDim.x) {
        const int n0 = tile * 32;
        __syncthreads();
        for (int i = tid; i < 1024; i += 256)
            ((float4*)shq)[i] = ((const float4*)g_h2)[(size_t)n0 * 32 + i];
        __syncthreads();

        float4 a0 = make_float4(0,0,0,0), a1 = a0, a2 = a0, a3 = a0;
        const float* q0 = shq + (ty * 4) * D;
        #pragma unroll 4
        for (int k = 0; k < D; k++) {
            const float4 wv = ((const float4*)shW)[k * 32 + tx];
            const float b0 = q0[k], b1 = q0[D + k], b2 = q0[2*D + k], b3 = q0[3*D + k];
            a0.x += b0*wv.x; a0.y += b0*wv.y; a0.z += b0*wv.z; a0.w += b0*wv.w;
            a1.x += b1*wv.x; a1.y += b1*wv.y; a1.z += b1*wv.z; a1.w += b1*wv.w;
            a2.x += b2*wv.x; a2.y += b2*wv.y; a2.z += b2*wv.z; a2.w += b2*wv.w;
            a3.x += b3*wv.x; a3.y += b3*wv.y; a3.z += b3*wv.z; a3.w += b3*wv.w;
        }
        ((float4*)outM)[(size_t)(n0 + ty*4 + 0) * 32 + tx] = a0;
        ((float4*)outM)[(size_t)(n0 + ty*4 + 1) * 32 + tx] = a1;
        ((float4*)outM)[(size_t)(n0 + ty*4 + 2) * 32 + tx] = a2;
        ((float4*)outM)[(size_t)(n0 + ty*4 + 3) * 32 + tx] = a3;
    }
}

// ---------------- launch ----------------
extern "C" void kernel_launch(void* const* d_in, const int* in_sizes, int n_in,
                              void* d_out, int out_size) {
    const float* pos  = (const float*)d_in[0];
    const float* h1   = (const float*)d_in[1];
    const float* t    = (const float*)d_in[2];
    const float* fw   = (const float*)d_in[3];
    const float* fb   = (const float*)d_in[4];
    const float* ln_g = (const float*)d_in[5];
    const float* ln_b = (const float*)d_in[6];
    const float* Wq   = (const float*)d_in[7];
    const float* Wk   = (const float*)d_in[8];
    const float* Wv   = (const float*)d_in[9];
    const float* Wo   = (const float*)d_in[10];
    const int* src    = (const int*)d_in[11];
    const int* dst    = (const int*)d_in[12];
    const int* q_id   = (const int*)d_in[13];

    float* out  = (float*)d_out;
    float* outM = out;                              // m_agg [N,D]
    float* outW = out + (size_t)N_NODES * D;        // W     [E,D]

    const size_t sm_k45 = (16384 + 16896 + 4096 + 4096) * sizeof(float) + 32 * sizeof(int); // ~166 KB
    const size_t sm_k7  = (16384 + 1024 + 4096 + 1024 + MAXD + 8 + 8 + 128) * sizeof(float); // ~91 KB
    const size_t sm_k8  = (16384 + 4096) * sizeof(float);                                    // 80 KB

    cudaFuncSetAttribute(k45_gk,  cudaFuncAttributeMaxDynamicSharedMemorySize, (int)sm_k45);
    cudaFuncSetAttribute(k7_node, cudaFuncAttributeMaxDynamicSharedMemorySize, (int)sm_k7);
    cudaFuncSetAttribute(k8_out,  cudaFuncAttributeMaxDynamicSharedMemorySize, (int)sm_k8);

    ka_histscan<<<148, 256>>>(src);                                   // 0
    k1_edge<<<N_EDGES / 64, 128>>>(pos, h1, t, fw, fb, ln_g, ln_b,
                                   src, dst, outW);                   // 1
    k45_gk<<<148, 256, sm_k45>>>(Wq, Wk, q_id);                       // 2
    k7_node<<<296, 128, sm_k7>>>(Wv);                                 // 3  <-- profiled
    k8_out<<<296, 256, sm_k8>>>(Wo, outM);                            // 4
}

// round 9
// speedup vs baseline: 3.2236x; 1.3940x over previous
#include <cuda_runtime.h>
#include <math.h>

#define N_NODES 20000
#define N_EDGES 320000
#define D 128
#define H 8
#define G 64
#define LN_EPS 1e-5f
#define WMAXD 64

#define WIDTH   (5.0f / 63.0f)
#define INV_W   (63.0f / 5.0f)
#define EXP_COEF (-0.5f * INV_W * INV_W)
#define PI_OVER_CUT 0.62831853071795864f
#define INV_SQRT_P 0.25f

// ---------------- scratch ----------------
static __device__ __align__(16) float g_q[(size_t)N_EDGES * D];     // SORTED by src
static __device__ float g_C[N_EDGES];                               // SORTED by src
static __device__ __align__(16) float g_gk[(size_t)N_NODES * H * D];
static __device__ __align__(16) float g_h2[(size_t)N_NODES * D];
static __device__ int g_hist[N_NODES];
static __device__ int g_off[N_NODES + 1];
static __device__ int g_cursor[N_NODES];
static __device__ int g_pos[N_EDGES];
static __device__ int g_done;

// ---------------- KA: fused histogram + scan ----------------
__global__ void __launch_bounds__(256) ka_histscan(const int* __restrict__ src) {
    for (int e = blockIdx.x * blockDim.x + threadIdx.x; e < N_EDGES;
         e += gridDim.x * blockDim.x)
        atomicAdd(&g_hist[src[e]], 1);
    __threadfence();
    __syncthreads();
    if (threadIdx.x == 0) atomicAdd(&g_done, 1);

    if (blockIdx.x != 0) return;
    if (threadIdx.x == 0) {
        while (*((volatile int*)&g_done) < (int)gridDim.x) { }
    }
    __syncthreads();
    __threadfence();

    __shared__ int sh[256];
    const int tid = threadIdx.x;
    const int CH = (N_NODES + 255) / 256;
    const int lo = tid * CH;
    const int hi = min(lo + CH, N_NODES);
    int s = 0;
    for (int i = lo; i < hi; i++) s += g_hist[i];
    sh[tid] = s;
    __syncthreads();
    for (int off = 1; off < 256; off <<= 1) {
        int v = (tid >= off) ? sh[tid - off] : 0;
        __syncthreads();
        sh[tid] += v;
        __syncthreads();
    }
    int base = (tid == 0) ? 0 : sh[tid - 1];
    for (int i = lo; i < hi; i++) {
        int c = g_hist[i];
        g_off[i] = base;
        g_cursor[i] = base;
        g_hist[i] = 0;
        base += c;
    }
    __syncthreads();
    if (tid == 0) { g_off[N_NODES] = N_EDGES; g_done = 0; }
}

// ---------------- K1: warp-per-edge; W (orig order) + q,C (sorted order) ----------------
__global__ void __launch_bounds__(128) k1_edge(
    const float* __restrict__ pos, const float* __restrict__ h1,
    const float* __restrict__ t,   const float* __restrict__ fw,
    const float* __restrict__ fb,  const float* __restrict__ ln_g,
    const float* __restrict__ ln_b,const int* __restrict__ src,
    const int* __restrict__ dst,   float* __restrict__ outW)
{
    __shared__ float4 sh_fw[G * 32];
    const int tid  = threadIdx.x;
    const int lane = tid & 31;
    const int w    = tid >> 5;

    for (int i = tid; i < G * 32; i += 128) sh_fw[i] = ((const float4*)fw)[i];
    __syncthreads();

    float4 colsum = make_float4(0.f, 0.f, 0.f, 0.f);
    #pragma unroll
    for (int g = 0; g < G; g++) {
        const float4 w4 = sh_fw[g * 32 + lane];
        colsum.x += w4.x; colsum.y += w4.y; colsum.z += w4.z; colsum.w += w4.w;
    }
    const float4 fb4 = ((const float4*)fb)[lane];
    const float4 lg4 = ((const float4*)ln_g)[lane];
    const float4 lb4 = ((const float4*)ln_b)[lane];

    const int e0 = blockIdx.x * 64 + w * 16;
    #pragma unroll 1
    for (int ei = 0; ei < 16; ei++) {
        const int e = e0 + ei;
        const int s = src[e], dn = dst[e];

        int p = 0;
        if (lane == 0) p = atomicAdd(&g_cursor[s], 1);
        p = __shfl_sync(0xffffffffu, p, 0);

        const float dx = pos[dn*3+0] - pos[s*3+0];
        const float dy = pos[dn*3+1] - pos[s*3+1];
        const float dz = pos[dn*3+2] - pos[s*3+2];
        const float r  = sqrtf(dx*dx + dy*dy + dz*dz);
        const float C  = (r < 5.0f) ? 0.5f * (__cosf(r * PI_OVER_CUT) + 1.0f) : 0.0f;

        const int i0  = __float2int_rn(r * INV_W);
        const int glo = max(0, i0 - 6);
        const int ghi = min(G - 1, i0 + 6);
        const int nwin = ghi - glo + 1;
        float myf = 0.f;
        if (lane < nwin) {
            const float dr = r - (glo + lane) * WIDTH;
            myf = __expf(EXP_COEF * dr * dr);
        }

        float4 acc = make_float4(0.f, 0.f, 0.f, 0.f);
        for (int j = 0; j < nwin; j++) {
            const float fj = __shfl_sync(0xffffffffu, myf, j);
            const float4 w4 = sh_fw[(glo + j) * 32 + lane];
            acc.x += fj * w4.x; acc.y += fj * w4.y;
            acc.z += fj * w4.z; acc.w += fj * w4.w;
        }
        float4 W4;
        W4.x = (2.0f * acc.x - colsum.x + fb4.x) * C;
        W4.y = (2.0f * acc.y - colsum.y + fb4.y) * C;
        W4.z = (2.0f * acc.z - colsum.z + fb4.z) * C;
        W4.w = (2.0f * acc.w - colsum.w + fb4.w) * C;
        ((float4*)outW)[(size_t)e * 32 + lane] = W4;

        const float4 h4 = ((const float4*)h1)[(size_t)dn * 32 + lane];
        const float4 t4 = ((const float4*)t)[(size_t)e * 32 + lane];
        float4 v;
        v.x = W4.x * h4.x + t4.x; v.y = W4.y * h4.y + t4.y;
        v.z = W4.z * h4.z + t4.z; v.w = W4.w * h4.w + t4.w;

        float sm = v.x + v.y + v.z + v.w;
        float sq = v.x*v.x + v.y*v.y + v.z*v.z + v.w*v.w;
        #pragma unroll
        for (int o = 16; o; o >>= 1) {
            sm += __shfl_xor_sync(0xffffffffu, sm, o);
            sq += __shfl_xor_sync(0xffffffffu, sq, o);
        }
        const float mu  = sm * (1.0f / D);
        const float var = sq * (1.0f / D) - mu * mu;
        const float inv = rsqrtf(var + LN_EPS);
        float4 qo;
        qo.x = (v.x - mu) * inv * lg4.x + lb4.x;
        qo.y = (v.y - mu) * inv * lg4.y + lb4.y;
        qo.z = (v.z - mu) * inv * lg4.z + lb4.z;
        qo.w = (v.w - mu) * inv * lg4.w + lb4.w;
        ((float4*)g_q)[(size_t)p * 32 + lane] = qo;

        if (lane == 0) { g_C[p] = C; g_pos[e] = p; }
    }
}

// ---------------- K45: qv (smem-resident) then gk, tiled 32 nodes ----------------
__global__ void __launch_bounds__(256) k45_gk(
    const float* __restrict__ Wq, const float* __restrict__ Wk,
    const int* __restrict__ q_id)
{
    extern __shared__ float sm[];
    float* shWq  = sm;                    // 16384
    float* shWkT = shWq + 16384;          // 128*132
    float* shq   = shWkT + 16896;         // 4096
    float* shqv  = shq + 4096;            // 4096
    int*   shIdx = (int*)(shqv + 4096);   // 32
    const int tid = threadIdx.x;
    const int tx = tid & 31, ty = tid >> 5;

    for (int i = tid; i < D * D; i += 256) shWq[i] = Wq[i];
    for (int i = tid; i < D * D; i += 256) {
        const int d = i >> 7, j = i & 127;
        shWkT[j * 132 + d] = Wk[i];
    }
    const float4* wrow = (const float4*)shWkT;   // row stride 33 float4

    for (int tile = blockIdx.x; tile < N_NODES / 32; tile += gridDim.x) {
        const int n0 = tile * 32;
        __syncthreads();
        if (tid < 32) shIdx[tid] = g_pos[q_id[n0 + tid]];
        __syncthreads();
        for (int i = tid; i < 1024; i += 256)
            ((float4*)shq)[i] = ((const float4*)g_q)[(size_t)shIdx[i >> 5] * 32 + (i & 31)];
        __syncthreads();

        {   // qv = shq @ Wq
            float4 a0 = make_float4(0,0,0,0), a1 = a0, a2 = a0, a3 = a0;
            const float* q0 = shq + (ty * 4) * D;
            #pragma unroll 4
            for (int k = 0; k < D; k++) {
                const float4 wv = ((const float4*)shWq)[k * 32 + tx];
                const float b0 = q0[k], b1 = q0[D + k], b2 = q0[2*D + k], b3 = q0[3*D + k];
                a0.x += b0*wv.x; a0.y += b0*wv.y; a0.z += b0*wv.z; a0.w += b0*wv.w;
                a1.x += b1*wv.x; a1.y += b1*wv.y; a1.z += b1*wv.z; a1.w += b1*wv.w;
                a2.x += b2*wv.x; a2.y += b2*wv.y; a2.z += b2*wv.z; a2.w += b2*wv.w;
                a3.x += b3*wv.x; a3.y += b3*wv.y; a3.z += b3*wv.z; a3.w += b3*wv.w;
            }
            ((float4*)shqv)[(ty*4 + 0) * 32 + tx] = a0;
            ((float4*)shqv)[(ty*4 + 1) * 32 + tx] = a1;
            ((float4*)shqv)[(ty*4 + 2) * 32 + tx] = a2;
            ((float4*)shqv)[(ty*4 + 3) * 32 + tx] = a3;
        }
        __syncthreads();

        {   // gk[n,h,:] = sum_p qv[n,h*16+p] * WkT[h*16+p, :]
            const int h = ty, c = tx;
            #pragma unroll 1
            for (int n = 0; n < 32; n++) {
                const float* qn = shqv + n * D + h * 16;
                float4 acc = make_float4(0,0,0,0);
                #pragma unroll
                for (int p = 0; p < 16; p++) {
                    const float a = qn[p];
                    const float4 w4 = wrow[(h*16 + p) * 33 + c];
                    acc.x += a*w4.x; acc.y += a*w4.y; acc.z += a*w4.z; acc.w += a*w4.w;
                }
                ((float4*)g_gk)[((size_t)(n0 + n) * H + h) * 32 + c] = acc;
            }
        }
    }
}

// ---------------- K7: WARP-PER-NODE attention + epilogue ----------------
__global__ void __launch_bounds__(256, 2) k7_node(const float* __restrict__ Wv) {
    extern __shared__ float sm[];
    float* shWv  = sm;                  // 16384 (64 KB)
    float* shBuf = shWv + 16384;        // 8 * 1024  per-warp logits/att -> Y
    float* shCb  = shBuf + 8192;        // 8 * 64    per-warp C
    float* shMS  = shCb + 512;          // 8 * 16    per-warp m / 1/s

    const int tid  = threadIdx.x;
    const int lane = tid & 31;
    const int w    = tid >> 5;
    float* myL = shBuf + w * 1024;
    float* myC = shCb + w * WMAXD;
    float* myM = shMS + w * 16;

    for (int i = tid; i < D * D; i += 256) shWv[i] = Wv[i];
    __syncthreads();

    for (int n = blockIdx.x * 8 + w; n < N_NODES; n += gridDim.x * 8) {
        const int base = g_off[n];
        const int deg  = g_off[n + 1] - base;
        if (deg == 0) {
            ((float4*)g_h2)[(size_t)n * 32 + lane] = make_float4(0,0,0,0);
            continue;
        }

        float4 g4[H];
        #pragma unroll
        for (int h = 0; h < H; h++)
            g4[h] = ((const float4*)g_gk)[((size_t)n * H + h) * 32 + lane];

        float4 Y[H];
        #pragma unroll
        for (int h = 0; h < H; h++) Y[h] = make_float4(0,0,0,0);

        if (deg <= WMAXD) {
            // FIX (R7 bug): strided load covers deg up to WMAXD, not just 32
            for (int j = lane; j < deg; j += 32) myC[j] = g_C[base + j];
            __syncwarp();

            // ---- pass A: logits + own-head max (26-shfl reduction) ----
            float mown = -1e30f;
            {
                float4 qn = ((const float4*)g_q)[(size_t)base * 32 + lane];
                for (int i = 0; i < deg; i++) {
                    const float4 q4 = qn;
                    if (i + 1 < deg)
                        qn = ((const float4*)g_q)[(size_t)(base + i + 1) * 32 + lane];
                    float pr0 = q4.x*g4[0].x + q4.y*g4[0].y + q4.z*g4[0].z + q4.w*g4[0].w;
                    float pr1 = q4.x*g4[1].x + q4.y*g4[1].y + q4.z*g4[1].z + q4.w*g4[1].w;
                    float pr2 = q4.x*g4[2].x + q4.y*g4[2].y + q4.z*g4[2].z + q4.w*g4[2].w;
                    float pr3 = q4.x*g4[3].x + q4.y*g4[3].y + q4.z*g4[3].z + q4.w*g4[3].w;
                    float pr4 = q4.x*g4[4].x + q4.y*g4[4].y + q4.z*g4[4].z + q4.w*g4[4].w;
                    float pr5 = q4.x*g4[5].x + q4.y*g4[5].y + q4.z*g4[5].z + q4.w*g4[5].w;
                    float pr6 = q4.x*g4[6].x + q4.y*g4[6].y + q4.z*g4[6].z + q4.w*g4[6].w;
                    float pr7 = q4.x*g4[7].x + q4.y*g4[7].y + q4.z*g4[7].z + q4.w*g4[7].w;
                    #pragma unroll
                    for (int off = 16; off >= 4; off >>= 1) {
                        pr0 += __shfl_xor_sync(0xffffffffu, pr0, off);
                        pr1 += __shfl_xor_sync(0xffffffffu, pr1, off);
                        pr2 += __shfl_xor_sync(0xffffffffu, pr2, off);
                        pr3 += __shfl_xor_sync(0xffffffffu, pr3, off);
                        pr4 += __shfl_xor_sync(0xffffffffu, pr4, off);
                        pr5 += __shfl_xor_sync(0xffffffffu, pr5, off);
                        pr6 += __shfl_xor_sync(0xffffffffu, pr6, off);
                        pr7 += __shfl_xor_sync(0xffffffffu, pr7, off);
                    }
                    const float t0 = (lane & 4) ? pr1 : pr0;
                    const float t1 = (lane & 4) ? pr3 : pr2;
                    const float t2 = (lane & 4) ? pr5 : pr4;
                    const float t3 = (lane & 4) ? pr7 : pr6;
                    const float u0 = (lane & 8) ? t1 : t0;
                    const float u1 = (lane & 8) ? t3 : t2;
                    float x = (lane & 16) ? u1 : u0;
                    x += __shfl_xor_sync(0xffffffffu, x, 2);
                    x += __shfl_xor_sync(0xffffffffu, x, 1);
                    x *= INV_SQRT_P;
                    if ((lane & 3) == 0) myL[i * 8 + (lane >> 2)] = x;
                    mown = fmaxf(mown, x);
                }
            }
            __syncwarp();
            if ((lane & 3) == 0) myM[lane >> 2] = mown;
            __syncwarp();

            // ---- pass B: att = exp(l-m)*C; warp-local per-head sums ----
            float sp = 0.f;
            const float mh = myM[lane & 7];
            for (int j = lane; j < deg * 8; j += 32) {
                const float v = __expf(myL[j] - mh) * myC[j >> 3];
                myL[j] = v;
                sp += v;
            }
            sp += __shfl_xor_sync(0xffffffffu, sp, 8);
            sp += __shfl_xor_sync(0xffffffffu, sp, 16);
            if (lane < 8) myM[8 + lane] = 1.0f / sp;
            __syncwarp();

            // ---- pass C: Y accumulation (shfl/exp-free) ----
            {
                float4 qn = ((const float4*)g_q)[(size_t)base * 32 + lane];
                for (int i = 0; i < deg; i++) {
                    const float4 q4 = qn;
                    if (i + 1 < deg)
                        qn = ((const float4*)g_q)[(size_t)(base + i + 1) * 32 + lane];
                    #pragma unroll
                    for (int h = 0; h < H; h++) {
                        const float a = myL[i * 8 + h];
                        Y[h].x += a * q4.x; Y[h].y += a * q4.y;
                        Y[h].z += a * q4.z; Y[h].w += a * q4.w;
                    }
                }
            }
            __syncwarp();
            #pragma unroll
            for (int h = 0; h < H; h++) {
                const float si = myM[8 + h];
                Y[h].x *= si; Y[h].y *= si; Y[h].z *= si; Y[h].w *= si;
                *(float4*)&myL[h * D + lane * 4] = Y[h];   // overwrite att with Y
            }
            __syncwarp();
        } else {
            // ---- fallback: warp-local flash online softmax ----
            float m[H], s[H];
            #pragma unroll
            for (int h = 0; h < H; h++) { m[h] = -1e30f; s[h] = 0.f; }
            for (int i = 0; i < deg; i++) {
                const float4 q4 = ((const float4*)g_q)[(size_t)(base + i) * 32 + lane];
                const float Ce = g_C[base + i];
                #pragma unroll
                for (int h = 0; h < H; h++) {
                    float pq = q4.x*g4[h].x + q4.y*g4[h].y + q4.z*g4[h].z + q4.w*g4[h].w;
                    #pragma unroll
                    for (int o = 16; o; o >>= 1) pq += __shfl_xor_sync(0xffffffffu, pq, o);
                    pq *= INV_SQRT_P;
                    const float nm = fmaxf(m[h], pq);
                    const float sc = __expf(m[h] - nm);
                    const float ww = __expf(pq - nm) * Ce;
                    s[h] = s[h] * sc + ww;
                    Y[h].x = Y[h].x * sc + ww * q4.x;
                    Y[h].y = Y[h].y * sc + ww * q4.y;
                    Y[h].z = Y[h].z * sc + ww * q4.z;
                    Y[h].w = Y[h].w * sc + ww * q4.w;
                    m[h] = nm;
                }
            }
            #pragma unroll
            for (int h = 0; h < H; h++) {
                const float si = 1.0f / s[h];
                Y[h].x *= si; Y[h].y *= si; Y[h].z *= si; Y[h].w *= si;
                *(float4*)&myL[h * D + lane * 4] = Y[h];
            }
            __syncwarp();
        }

        // ---- epilogue: h2[j] = sum_d Y[j>>4, d] * Wv[d, j] ----
        const float* yrow = myL + (lane >> 2) * D;
        float4 hv = make_float4(0,0,0,0);
        #pragma unroll 8
        for (int d = 0; d < D; d += 4) {
            const float4 y4 = *(const float4*)&yrow[d];
            const float4 w0 = ((const float4*)shWv)[(d+0) * 32 + lane];
            const float4 w1 = ((const float4*)shWv)[(d+1) * 32 + lane];
            const float4 w2 = ((const float4*)shWv)[(d+2) * 32 + lane];
            const float4 w3 = ((const float4*)shWv)[(d+3) * 32 + lane];
            hv.x += y4.x*w0.x + y4.y*w1.x + y4.z*w2.x + y4.w*w3.x;
            hv.y += y4.x*w0.y + y4.y*w1.y + y4.z*w2.y + y4.w*w3.y;
            hv.z += y4.x*w0.z + y4.y*w1.z + y4.z*w2.z + y4.w*w3.z;
            hv.w += y4.x*w0.w + y4.y*w1.w + y4.z*w2.w + y4.w*w3.w;
        }
        ((float4*)g_h2)[(size_t)n * 32 + lane] = hv;
    }
}

// ---------------- K8: tiled m_agg = h2 @ Wo ----------------
__global__ void __launch_bounds__(256) k8_out(const float* __restrict__ Wo,
                                              float* __restrict__ outM) {
    extern __shared__ float sm[];
    float* shW = sm;             // 16384
    float* shq = shW + 16384;    // 4096
    const int tid = threadIdx.x;
    const int tx = tid & 31, ty = tid >> 5;

    for (int i = tid; i < D * D; i += 256) shW[i] = Wo[i];

    for (int tile = blockIdx.x; tile < N_NODES / 32; tile += gridDim.x) {
        const int n0 = tile * 32;
        __syncthreads();
        for (int i = tid; i < 1024; i += 256)
            ((float4*)shq)[i] = ((const float4*)g_h2)[(size_t)n0 * 32 + i];
        __syncthreads();

        float4 a0 = make_float4(0,0,0,0), a1 = a0, a2 = a0, a3 = a0;
        const float* q0 = shq + (ty * 4) * D;
        #pragma unroll 4
        for (int k = 0; k < D; k++) {
            const float4 wv = ((const float4*)shW)[k * 32 + tx];
            const float b0 = q0[k], b1 = q0[D + k], b2 = q0[2*D + k], b3 = q0[3*D + k];
            a0.x += b0*wv.x; a0.y += b0*wv.y; a0.z += b0*wv.z; a0.w += b0*wv.w;
            a1.x += b1*wv.x; a1.y += b1*wv.y; a1.z += b1*wv.z; a1.w += b1*wv.w;
            a2.x += b2*wv.x; a2.y += b2*wv.y; a2.z += b2*wv.z; a2.w += b2*wv.w;
            a3.x += b3*wv.x; a3.y += b3*wv.y; a3.z += b3*wv.z; a3.w += b3*wv.w;
        }
        ((float4*)outM)[(size_t)(n0 + ty*4 + 0) * 32 + tx] = a0;
        ((float4*)outM)[(size_t)(n0 + ty*4 + 1) * 32 + tx] = a1;
        ((float4*)outM)[(size_t)(n0 + ty*4 + 2) * 32 + tx] = a2;
        ((float4*)outM)[(size_t)(n0 + ty*4 + 3) * 32 + tx] = a3;
    }
}

// ---------------- launch ----------------
extern "C" void kernel_launch(void* const* d_in, const int* in_sizes, int n_in,
                              void* d_out, int out_size) {
    const float* pos  = (const float*)d_in[0];
    const float* h1   = (const float*)d_in[1];
    const float* t    = (const float*)d_in[2];
    const float* fw   = (const float*)d_in[3];
    const float* fb   = (const float*)d_in[4];
    const float* ln_g = (const float*)d_in[5];
    const float* ln_b = (const float*)d_in[6];
    const float* Wq   = (const float*)d_in[7];
    const float* Wk   = (const float*)d_in[8];
    const float* Wv   = (const float*)d_in[9];
    const float* Wo   = (const float*)d_in[10];
    const int* src    = (const int*)d_in[11];
    const int* dst    = (const int*)d_in[12];
    const int* q_id   = (const int*)d_in[13];

    float* out  = (float*)d_out;
    float* outM = out;                              // m_agg [N,D]
    float* outW = out + (size_t)N_NODES * D;        // W     [E,D]

    const size_t sm_k45 = (16384 + 16896 + 4096 + 4096) * sizeof(float) + 32 * sizeof(int);
    const size_t sm_k7  = (16384 + 8192 + 512 + 128) * sizeof(float);   // 100,864 B
    const size_t sm_k8  = (16384 + 4096) * sizeof(float);

    cudaFuncSetAttribute(k45_gk,  cudaFuncAttributeMaxDynamicSharedMemorySize, (int)sm_k45);
    cudaFuncSetAttribute(k7_node, cudaFuncAttributeMaxDynamicSharedMemorySize, (int)sm_k7);
    cudaFuncSetAttribute(k8_out,  cudaFuncAttributeMaxDynamicSharedMemorySize, (int)sm_k8);

    ka_histscan<<<148, 256>>>(src);                                   // 0
    k1_edge<<<N_EDGES / 64, 128>>>(pos, h1, t, fw, fb, ln_g, ln_b,
                                   src, dst, outW);                   // 1
    k45_gk<<<148, 256, sm_k45>>>(Wq, Wk, q_id);                       // 2
    k7_node<<<296, 256, sm_k7>>>(Wv);                                 // 3  <-- profiled
    k8_out<<<296, 256, sm_k8>>>(Wo, outM);                            // 4
}

// round 10
// speedup vs baseline: 3.9523x; 1.2261x over previous
#include <cuda_runtime.h>
#include <math.h>

#define N_NODES 20000
#define N_EDGES 320000
#define D 128
#define H 8
#define G 64
#define LN_EPS 1e-5f
#define WMAXD 64

#define WIDTH   (5.0f / 63.0f)
#define INV_W   (63.0f / 5.0f)
#define EXP_COEF (-0.5f * INV_W * INV_W)
#define PI_OVER_CUT 0.62831853071795864f
#define INV_SQRT_P 0.25f

// ---------------- scratch ----------------
static __device__ __align__(16) float g_q[(size_t)N_EDGES * D];     // SORTED by src
static __device__ float g_C[N_EDGES];                               // SORTED by src
static __device__ __align__(16) float g_gk[(size_t)N_NODES * H * D];
static __device__ __align__(16) float g_h2[(size_t)N_NODES * D];
static __device__ int g_hist[N_NODES];
static __device__ int g_off[N_NODES + 1];
static __device__ int g_cursor[N_NODES];
static __device__ int g_pos[N_EDGES];
static __device__ int g_done;

// ---------------- KA: fused histogram + scan ----------------
__global__ void __launch_bounds__(256) ka_histscan(const int* __restrict__ src) {
    for (int e = blockIdx.x * blockDim.x + threadIdx.x; e < N_EDGES;
         e += gridDim.x * blockDim.x)
        atomicAdd(&g_hist[src[e]], 1);
    __threadfence();
    __syncthreads();
    if (threadIdx.x == 0) atomicAdd(&g_done, 1);

    if (blockIdx.x != 0) return;
    if (threadIdx.x == 0) {
        while (*((volatile int*)&g_done) < (int)gridDim.x) { }
    }
    __syncthreads();
    __threadfence();

    __shared__ int sh[256];
    const int tid = threadIdx.x;
    const int CH = (N_NODES + 255) / 256;
    const int lo = tid * CH;
    const int hi = min(lo + CH, N_NODES);
    int s = 0;
    for (int i = lo; i < hi; i++) s += g_hist[i];
    sh[tid] = s;
    __syncthreads();
    for (int off = 1; off < 256; off <<= 1) {
        int v = (tid >= off) ? sh[tid - off] : 0;
        __syncthreads();
        sh[tid] += v;
        __syncthreads();
    }
    int base = (tid == 0) ? 0 : sh[tid - 1];
    for (int i = lo; i < hi; i++) {
        int c = g_hist[i];
        g_off[i] = base;
        g_cursor[i] = base;
        g_hist[i] = 0;
        base += c;
    }
    __syncthreads();
    if (tid == 0) { g_off[N_NODES] = N_EDGES; g_done = 0; }
}

// ---------------- K1: warp-per-edge; parallel scalar phase; 9-tap window ----------------
__global__ void __launch_bounds__(128) k1_edge(
    const float* __restrict__ pos, const float* __restrict__ h1,
    const float* __restrict__ t,   const float* __restrict__ fw,
    const float* __restrict__ fb,  const float* __restrict__ ln_g,
    const float* __restrict__ ln_b,const int* __restrict__ src,
    const int* __restrict__ dst,   float* __restrict__ outW)
{
    __shared__ float4 sh_fw[G * 32];
    const int tid  = threadIdx.x;
    const int lane = tid & 31;
    const int w    = tid >> 5;
    const unsigned FULL = 0xffffffffu;

    for (int i = tid; i < G * 32; i += 128) sh_fw[i] = ((const float4*)fw)[i];
    __syncthreads();

    float4 colsum = make_float4(0.f, 0.f, 0.f, 0.f);
    #pragma unroll
    for (int g = 0; g < G; g++) {
        const float4 w4 = sh_fw[g * 32 + lane];
        colsum.x += w4.x; colsum.y += w4.y; colsum.z += w4.z; colsum.w += w4.w;
    }
    const float4 fb4 = ((const float4*)fb)[lane];
    const float4 lg4 = ((const float4*)ln_g)[lane];
    const float4 lb4 = ((const float4*)ln_b)[lane];

    const int e0 = blockIdx.x * 64 + w * 16;

    // ---- scalar phase: lanes 0..15 handle one edge each ----
    int dn_me = 0, p_me = 0, glo_me = 0, nwin_me = 0;
    float r_me = 0.f, C_me = 0.f;
    if (lane < 16) {
        const int e = e0 + lane;
        const int s = src[e];
        dn_me = dst[e];
        const float dx = pos[dn_me*3+0] - pos[s*3+0];
        const float dy = pos[dn_me*3+1] - pos[s*3+1];
        const float dz = pos[dn_me*3+2] - pos[s*3+2];
        r_me = sqrtf(dx*dx + dy*dy + dz*dz);
        C_me = (r_me < 5.0f) ? 0.5f * (__cosf(r_me * PI_OVER_CUT) + 1.0f) : 0.0f;
        const int i0 = __float2int_rn(r_me * INV_W);
        glo_me = max(0, i0 - 4);
        const int ghi = min(G - 1, i0 + 4);
        nwin_me = ghi - glo_me + 1;               // <= 9
        p_me = atomicAdd(&g_cursor[s], 1);
        g_pos[e] = p_me;
        g_C[p_me] = C_me;
    }

    // prefetch edge 0's h1/t rows
    int dn_nx = __shfl_sync(FULL, dn_me, 0);
    float4 h4n = ((const float4*)h1)[(size_t)dn_nx * 32 + lane];
    float4 t4n = ((const float4*)t)[(size_t)e0 * 32 + lane];

    #pragma unroll 1
    for (int ei = 0; ei < 16; ei++) {
        const int e = e0 + ei;
        const float4 h4 = h4n;
        const float4 t4 = t4n;
        if (ei + 1 < 16) {
            dn_nx = __shfl_sync(FULL, dn_me, ei + 1);
            h4n = ((const float4*)h1)[(size_t)dn_nx * 32 + lane];
            t4n = ((const float4*)t)[(size_t)(e + 1) * 32 + lane];
        }
        const int   p_e   = __shfl_sync(FULL, p_me, ei);
        const float C_e   = __shfl_sync(FULL, C_me, ei);
        const float r_e   = __shfl_sync(FULL, r_me, ei);
        const int   glo_e = __shfl_sync(FULL, glo_me, ei);
        const int   nwin_e= __shfl_sync(FULL, nwin_me, ei);

        float myf = 0.f;
        if (lane < nwin_e) {
            const float dr = r_e - (glo_e + lane) * WIDTH;
            myf = __expf(EXP_COEF * dr * dr);
        }

        float4 acc = make_float4(0.f, 0.f, 0.f, 0.f);
        for (int j = 0; j < nwin_e; j++) {
            const float fj = __shfl_sync(FULL, myf, j);
            const float4 w4 = sh_fw[(glo_e + j) * 32 + lane];
            acc.x += fj * w4.x; acc.y += fj * w4.y;
            acc.z += fj * w4.z; acc.w += fj * w4.w;
        }
        float4 W4;
        W4.x = (2.0f * acc.x - colsum.x + fb4.x) * C_e;
        W4.y = (2.0f * acc.y - colsum.y + fb4.y) * C_e;
        W4.z = (2.0f * acc.z - colsum.z + fb4.z) * C_e;
        W4.w = (2.0f * acc.w - colsum.w + fb4.w) * C_e;
        ((float4*)outW)[(size_t)e * 32 + lane] = W4;

        float4 v;
        v.x = W4.x * h4.x + t4.x; v.y = W4.y * h4.y + t4.y;
        v.z = W4.z * h4.z + t4.z; v.w = W4.w * h4.w + t4.w;

        float sm = v.x + v.y + v.z + v.w;
        float sq = v.x*v.x + v.y*v.y + v.z*v.z + v.w*v.w;
        #pragma unroll
        for (int o = 16; o; o >>= 1) {
            sm += __shfl_xor_sync(FULL, sm, o);
            sq += __shfl_xor_sync(FULL, sq, o);
        }
        const float mu  = sm * (1.0f / D);
        const float var = sq * (1.0f / D) - mu * mu;
        const float inv = rsqrtf(var + LN_EPS);
        float4 qo;
        qo.x = (v.x - mu) * inv * lg4.x + lb4.x;
        qo.y = (v.y - mu) * inv * lg4.y + lb4.y;
        qo.z = (v.z - mu) * inv * lg4.z + lb4.z;
        qo.w = (v.w - mu) * inv * lg4.w + lb4.w;
        ((float4*)g_q)[(size_t)p_e * 32 + lane] = qo;
    }
}

// ---------------- K45: qv (smem-resident) then gk, tiled 32 nodes ----------------
__global__ void __launch_bounds__(256) k45_gk(
    const float* __restrict__ Wq, const float* __restrict__ Wk,
    const int* __restrict__ q_id)
{
    extern __shared__ float sm[];
    float* shWq  = sm;                    // 16384
    float* shWkT = shWq + 16384;          // 128*132
    float* shq   = shWkT + 16896;         // 4096
    float* shqv  = shq + 4096;            // 4096
    int*   shIdx = (int*)(shqv + 4096);   // 32
    const int tid = threadIdx.x;
    const int tx = tid & 31, ty = tid >> 5;

    for (int i = tid; i < D * D; i += 256) shWq[i] = Wq[i];
    for (int i = tid; i < D * D; i += 256) {
        const int d = i >> 7, j = i & 127;
        shWkT[j * 132 + d] = Wk[i];
    }
    const float4* wrow = (const float4*)shWkT;   // row stride 33 float4

    for (int tile = blockIdx.x; tile < N_NODES / 32; tile += gridDim.x) {
        const int n0 = tile * 32;
        __syncthreads();
        if (tid < 32) shIdx[tid] = g_pos[q_id[n0 + tid]];
        __syncthreads();
        for (int i = tid; i < 1024; i += 256)
            ((float4*)shq)[i] = ((const float4*)g_q)[(size_t)shIdx[i >> 5] * 32 + (i & 31)];
        __syncthreads();

        {   // qv = shq @ Wq
            float4 a0 = make_float4(0,0,0,0), a1 = a0, a2 = a0, a3 = a0;
            const float* q0 = shq + (ty * 4) * D;
            #pragma unroll 4
            for (int k = 0; k < D; k++) {
                const float4 wv = ((const float4*)shWq)[k * 32 + tx];
                const float b0 = q0[k], b1 = q0[D + k], b2 = q0[2*D + k], b3 = q0[3*D + k];
                a0.x += b0*wv.x; a0.y += b0*wv.y; a0.z += b0*wv.z; a0.w += b0*wv.w;
                a1.x += b1*wv.x; a1.y += b1*wv.y; a1.z += b1*wv.z; a1.w += b1*wv.w;
                a2.x += b2*wv.x; a2.y += b2*wv.y; a2.z += b2*wv.z; a2.w += b2*wv.w;
                a3.x += b3*wv.x; a3.y += b3*wv.y; a3.z += b3*wv.z; a3.w += b3*wv.w;
            }
            ((float4*)shqv)[(ty*4 + 0) * 32 + tx] = a0;
            ((float4*)shqv)[(ty*4 + 1) * 32 + tx] = a1;
            ((float4*)shqv)[(ty*4 + 2) * 32 + tx] = a2;
            ((float4*)shqv)[(ty*4 + 3) * 32 + tx] = a3;
        }
        __syncthreads();

        {   // gk[n,h,:] = sum_p qv[n,h*16+p] * WkT[h*16+p, :]
            const int h = ty, c = tx;
            #pragma unroll 1
            for (int n = 0; n < 32; n++) {
                const float* qn = shqv + n * D + h * 16;
                float4 acc = make_float4(0,0,0,0);
                #pragma unroll
                for (int p = 0; p < 16; p++) {
                    const float a = qn[p];
                    const float4 w4 = wrow[(h*16 + p) * 33 + c];
                    acc.x += a*w4.x; acc.y += a*w4.y; acc.z += a*w4.z; acc.w += a*w4.w;
                }
                ((float4*)g_gk)[((size_t)(n0 + n) * H + h) * 32 + c] = acc;
            }
        }
    }
}

// ---------------- K7: WARP-PER-NODE, SINGLE-PASS unshifted softmax ----------------
// att = exp(l)*C / sum(exp(l)*C): shift-invariance makes max-subtraction unnecessary;
// logits are O(10) here (LN-normalized projections), exp() safe in fp32.
__global__ void __launch_bounds__(256, 2) k7_node(const float* __restrict__ Wv) {
    extern __shared__ float sm[];
    float* shWv  = sm;                  // 16384 (64 KB)
    float* shBuf = shWv + 16384;        // 8 * 1024  per-warp Y staging
    float* shCb  = shBuf + 8192;        // 8 * 64    per-warp C

    const int tid  = threadIdx.x;
    const int lane = tid & 31;
    const int w    = tid >> 5;
    const unsigned FULL = 0xffffffffu;
    float* myL = shBuf + w * 1024;
    float* myC = shCb + w * WMAXD;

    for (int i = tid; i < D * D; i += 256) shWv[i] = Wv[i];
    __syncthreads();

    for (int n = blockIdx.x * 8 + w; n < N_NODES; n += gridDim.x * 8) {
        const int base = g_off[n];
        const int deg  = g_off[n + 1] - base;
        if (deg == 0) {
            ((float4*)g_h2)[(size_t)n * 32 + lane] = make_float4(0,0,0,0);
            continue;
        }

        float4 g4[H];
        #pragma unroll
        for (int h = 0; h < H; h++)
            g4[h] = ((const float4*)g_gk)[((size_t)n * H + h) * 32 + lane];

        float4 Y[H];
        #pragma unroll
        for (int h = 0; h < H; h++) Y[h] = make_float4(0,0,0,0);

        if (deg <= WMAXD) {
            for (int j = lane; j < deg; j += 32) myC[j] = g_C[base + j];
            __syncwarp();

            float s_own = 0.f;                 // sum for head (lane>>2)
            float4 qn = ((const float4*)g_q)[(size_t)base * 32 + lane];
            for (int i = 0; i < deg; i++) {
                const float4 q4 = qn;
                const float Ce = myC[i];
                if (i + 1 < deg)
                    qn = ((const float4*)g_q)[(size_t)(base + i + 1) * 32 + lane];
                float pr0 = q4.x*g4[0].x + q4.y*g4[0].y + q4.z*g4[0].z + q4.w*g4[0].w;
                float pr1 = q4.x*g4[1].x + q4.y*g4[1].y + q4.z*g4[1].z + q4.w*g4[1].w;
                float pr2 = q4.x*g4[2].x + q4.y*g4[2].y + q4.z*g4[2].z + q4.w*g4[2].w;
                float pr3 = q4.x*g4[3].x + q4.y*g4[3].y + q4.z*g4[3].z + q4.w*g4[3].w;
                float pr4 = q4.x*g4[4].x + q4.y*g4[4].y + q4.z*g4[4].z + q4.w*g4[4].w;
                float pr5 = q4.x*g4[5].x + q4.y*g4[5].y + q4.z*g4[5].z + q4.w*g4[5].w;
                float pr6 = q4.x*g4[6].x + q4.y*g4[6].y + q4.z*g4[6].z + q4.w*g4[6].w;
                float pr7 = q4.x*g4[7].x + q4.y*g4[7].y + q4.z*g4[7].z + q4.w*g4[7].w;
                #pragma unroll
                for (int off = 16; off >= 4; off >>= 1) {
                    pr0 += __shfl_xor_sync(FULL, pr0, off);
                    pr1 += __shfl_xor_sync(FULL, pr1, off);
                    pr2 += __shfl_xor_sync(FULL, pr2, off);
                    pr3 += __shfl_xor_sync(FULL, pr3, off);
                    pr4 += __shfl_xor_sync(FULL, pr4, off);
                    pr5 += __shfl_xor_sync(FULL, pr5, off);
                    pr6 += __shfl_xor_sync(FULL, pr6, off);
                    pr7 += __shfl_xor_sync(FULL, pr7, off);
                }
                const float t0 = (lane & 4) ? pr1 : pr0;
                const float t1 = (lane & 4) ? pr3 : pr2;
                const float t2 = (lane & 4) ? pr5 : pr4;
                const float t3 = (lane & 4) ? pr7 : pr6;
                const float u0 = (lane & 8) ? t1 : t0;
                const float u1 = (lane & 8) ? t3 : t2;
                float x = (lane & 16) ? u1 : u0;
                x += __shfl_xor_sync(FULL, x, 2);
                x += __shfl_xor_sync(FULL, x, 1);
                // x = logit of head (lane>>2), replicated across each 4-lane group
                const float a = __expf(x * INV_SQRT_P) * Ce;
                s_own += a;
                const float a0 = __shfl_sync(FULL, a, 0);
                const float a1 = __shfl_sync(FULL, a, 4);
                const float a2 = __shfl_sync(FULL, a, 8);
                const float a3 = __shfl_sync(FULL, a, 12);
                const float a4 = __shfl_sync(FULL, a, 16);
                const float a5 = __shfl_sync(FULL, a, 20);
                const float a6 = __shfl_sync(FULL, a, 24);
                const float a7 = __shfl_sync(FULL, a, 28);
                Y[0].x += a0*q4.x; Y[0].y += a0*q4.y; Y[0].z += a0*q4.z; Y[0].w += a0*q4.w;
                Y[1].x += a1*q4.x; Y[1].y += a1*q4.y; Y[1].z += a1*q4.z; Y[1].w += a1*q4.w;
                Y[2].x += a2*q4.x; Y[2].y += a2*q4.y; Y[2].z += a2*q4.z; Y[2].w += a2*q4.w;
                Y[3].x += a3*q4.x; Y[3].y += a3*q4.y; Y[3].z += a3*q4.z; Y[3].w += a3*q4.w;
                Y[4].x += a4*q4.x; Y[4].y += a4*q4.y; Y[4].z += a4*q4.z; Y[4].w += a4*q4.w;
                Y[5].x += a5*q4.x; Y[5].y += a5*q4.y; Y[5].z += a5*q4.z; Y[5].w += a5*q4.w;
                Y[6].x += a6*q4.x; Y[6].y += a6*q4.y; Y[6].z += a6*q4.z; Y[6].w += a6*q4.w;
                Y[7].x += a7*q4.x; Y[7].y += a7*q4.y; Y[7].z += a7*q4.z; Y[7].w += a7*q4.w;
            }
            #pragma unroll
            for (int h = 0; h < H; h++) {
                const float sh_ = __shfl_sync(FULL, s_own, h << 2);
                const float si = 1.0f / sh_;
                Y[h].x *= si; Y[h].y *= si; Y[h].z *= si; Y[h].w *= si;
                *(float4*)&myL[h * D + lane * 4] = Y[h];
            }
            __syncwarp();
        } else {
            // ---- fallback: warp-local flash online softmax (rare) ----
            float m[H], s[H];
            #pragma unroll
            for (int h = 0; h < H; h++) { m[h] = -1e30f; s[h] = 0.f; }
            for (int i = 0; i < deg; i++) {
                const float4 q4 = ((const float4*)g_q)[(size_t)(base + i) * 32 + lane];
                const float Ce = g_C[base + i];
                #pragma unroll
                for (int h = 0; h < H; h++) {
                    float pq = q4.x*g4[h].x + q4.y*g4[h].y + q4.z*g4[h].z + q4.w*g4[h].w;
                    #pragma unroll
                    for (int o = 16; o; o >>= 1) pq += __shfl_xor_sync(FULL, pq, o);
                    pq *= INV_SQRT_P;
                    const float nm = fmaxf(m[h], pq);
                    const float sc = __expf(m[h] - nm);
                    const float ww = __expf(pq - nm) * Ce;
                    s[h] = s[h] * sc + ww;
                    Y[h].x = Y[h].x * sc + ww * q4.x;
                    Y[h].y = Y[h].y * sc + ww * q4.y;
                    Y[h].z = Y[h].z * sc + ww * q4.z;
                    Y[h].w = Y[h].w * sc + ww * q4.w;
                    m[h] = nm;
                }
            }
            #pragma unroll
            for (int h = 0; h < H; h++) {
                const float si = 1.0f / s[h];
                Y[h].x *= si; Y[h].y *= si; Y[h].z *= si; Y[h].w *= si;
                *(float4*)&myL[h * D + lane * 4] = Y[h];
            }
            __syncwarp();
        }

        // ---- epilogue: h2[j] = sum_d Y[j>>4, d] * Wv[d, j] ----
        const float* yrow = myL + (lane >> 2) * D;
        float4 hv = make_float4(0,0,0,0);
        #pragma unroll 8
        for (int d = 0; d < D; d += 4) {
            const float4 y4 = *(const float4*)&yrow[d];
            const float4 w0 = ((const float4*)shWv)[(d+0) * 32 + lane];
            const float4 w1 = ((const float4*)shWv)[(d+1) * 32 + lane];
            const float4 w2 = ((const float4*)shWv)[(d+2) * 32 + lane];
            const float4 w3 = ((const float4*)shWv)[(d+3) * 32 + lane];
            hv.x += y4.x*w0.x + y4.y*w1.x + y4.z*w2.x + y4.w*w3.x;
            hv.y += y4.x*w0.y + y4.y*w1.y + y4.z*w2.y + y4.w*w3.y;
            hv.z += y4.x*w0.z + y4.y*w1.z + y4.z*w2.z + y4.w*w3.z;
            hv.w += y4.x*w0.w + y4.y*w1.w + y4.z*w2.w + y4.w*w3.w;
        }
        ((float4*)g_h2)[(size_t)n * 32 + lane] = hv;
    }
}

// ---------------- K8: tiled m_agg = h2 @ Wo ----------------
__global__ void __launch_bounds__(256) k8_out(const float* __restrict__ Wo,
                                              float* __restrict__ outM) {
    extern __shared__ float sm[];
    float* shW = sm;             // 16384
    float* shq = shW + 16384;    // 4096
    const int tid = threadIdx.x;
    const int tx = tid & 31, ty = tid >> 5;

    for (int i = tid; i < D * D; i += 256) shW[i] = Wo[i];

    for (int tile = blockIdx.x; tile < N_NODES / 32; tile += gridDim.x) {
        const int n0 = tile * 32;
        __syncthreads();
        for (int i = tid; i < 1024; i += 256)
            ((float4*)shq)[i] = ((const float4*)g_h2)[(size_t)n0 * 32 + i];
        __syncthreads();

        float4 a0 = make_float4(0,0,0,0), a1 = a0, a2 = a0, a3 = a0;
        const float* q0 = shq + (ty * 4) * D;
        #pragma unroll 4
        for (int k = 0; k < D; k++) {
            const float4 wv = ((const float4*)shW)[k * 32 + tx];
            const float b0 = q0[k], b1 = q0[D + k], b2 = q0[2*D + k], b3 = q0[3*D + k];
            a0.x += b0*wv.x; a0.y += b0*wv.y; a0.z += b0*wv.z; a0.w += b0*wv.w;
            a1.x += b1*wv.x; a1.y += b1*wv.y; a1.z += b1*wv.z; a1.w += b1*wv.w;
            a2.x += b2*wv.x; a2.y += b2*wv.y; a2.z += b2*wv.z; a2.w += b2*wv.w;
            a3.x += b3*wv.x; a3.y += b3*wv.y; a3.z += b3*wv.z; a3.w += b3*wv.w;
        }
        ((float4*)outM)[(size_t)(n0 + ty*4 + 0) * 32 + tx] = a0;
        ((float4*)outM)[(size_t)(n0 + ty*4 + 1) * 32 + tx] = a1;
        ((float4*)outM)[(size_t)(n0 + ty*4 + 2) * 32 + tx] = a2;
        ((float4*)outM)[(size_t)(n0 + ty*4 + 3) * 32 + tx] = a3;
    }
}

// ---------------- launch ----------------
extern "C" void kernel_launch(void* const* d_in, const int* in_sizes, int n_in,
                              void* d_out, int out_size) {
    const float* pos  = (const float*)d_in[0];
    const float* h1   = (const float*)d_in[1];
    const float* t    = (const float*)d_in[2];
    const float* fw   = (const float*)d_in[3];
    const float* fb   = (const float*)d_in[4];
    const float* ln_g = (const float*)d_in[5];
    const float* ln_b = (const float*)d_in[6];
    const float* Wq   = (const float*)d_in[7];
    const float* Wk   = (const float*)d_in[8];
    const float* Wv   = (const float*)d_in[9];
    const float* Wo   = (const float*)d_in[10];
    const int* src    = (const int*)d_in[11];
    const int* dst    = (const int*)d_in[12];
    const int* q_id   = (const int*)d_in[13];

    float* out  = (float*)d_out;
    float* outM = out;                              // m_agg [N,D]
    float* outW = out + (size_t)N_NODES * D;        // W     [E,D]

    const size_t sm_k45 = (16384 + 16896 + 4096 + 4096) * sizeof(float) + 32 * sizeof(int);
    const size_t sm_k7  = (16384 + 8192 + 512) * sizeof(float);   // 100,352 B
    const size_t sm_k8  = (16384 + 4096) * sizeof(float);

    cudaFuncSetAttribute(k45_gk,  cudaFuncAttributeMaxDynamicSharedMemorySize, (int)sm_k45);
    cudaFuncSetAttribute(k7_node, cudaFuncAttributeMaxDynamicSharedMemorySize, (int)sm_k7);
    cudaFuncSetAttribute(k8_out,  cudaFuncAttributeMaxDynamicSharedMemorySize, (int)sm_k8);

    ka_histscan<<<148, 256>>>(src);                                   // 0
    k1_edge<<<N_EDGES / 64, 128>>>(pos, h1, t, fw, fb, ln_g, ln_b,
                                   src, dst, outW);                   // 1
    k45_gk<<<148, 256, sm_k45>>>(Wq, Wk, q_id);                       // 2
    k7_node<<<296, 256, sm_k7>>>(Wv);                                 // 3  <-- profiled
    k8_out<<<296, 256, sm_k8>>>(Wo, outM);                            // 4
}